// round 8
// baseline (speedup 1.0000x reference)
#include <cuda_runtime.h>
#include <math.h>

#define BB 16
#define CC 128
#define LL 16384
#define LK 4096
#define NH 8
#define DH 16

typedef unsigned long long ull;

// ------------------- scratch (device globals; no allocations) -------------------
__device__ float g_dwq[BB*CC*LL];
__device__ float g_dwk[BB*CC*LK];
__device__ float g_dwv[BB*CC*LK];
__device__ float g_k  [BB*CC*LK];
__device__ float g_v  [BB*CC*LK];
__device__ float g_z  [BB*CC*LL];
__device__ float g_pre[BB*CC*LL];
__device__ float g_kv [BB*NH*DH*DH];
__device__ float g_km [BB*CC];
__device__ float g_kis[BB*CC];
__device__ float g_weff[3*CC*CC];
__device__ float g_beff[3*CC];
__device__ float g_A1[CC], g_B1[CC], g_A2[CC], g_B2[CC];
// slots: 0/1 dwq, 2/3 dwk, 4/5 dwv, 6/7 z, 8/9 pre
__device__ double g_stats[10*CC];

// ------------------- helpers -------------------
__device__ __forceinline__ float geluf(float x){
    return 0.5f * x * (1.0f + erff(x * 0.70710678118654752440f));
}
__device__ __forceinline__ float warpRedSum(float v){
    v += __shfl_xor_sync(0xffffffffu, v, 16);
    v += __shfl_xor_sync(0xffffffffu, v, 8);
    v += __shfl_xor_sync(0xffffffffu, v, 4);
    v += __shfl_xor_sync(0xffffffffu, v, 2);
    v += __shfl_xor_sync(0xffffffffu, v, 1);
    return v;
}
__device__ __forceinline__ ull pack2(float lo, float hi){
    ull r; unsigned a = __float_as_uint(lo), b = __float_as_uint(hi);
    asm("mov.b64 %0, {%1,%2};" : "=l"(r) : "r"(a), "r"(b));
    return r;
}
__device__ __forceinline__ void unpack2(ull v, float& lo, float& hi){
    unsigned a, b;
    asm("mov.b64 {%0,%1}, %2;" : "=r"(a), "=r"(b) : "l"(v));
    lo = __uint_as_float(a); hi = __uint_as_float(b);
}
__device__ __forceinline__ ull fma2(ull a, ull b, ull c){
    ull d;
    asm("fma.rn.f32x2 %0, %1, %2, %3;" : "=l"(d) : "l"(a), "l"(b), "l"(c));
    return d;
}

__device__ __forceinline__ void blockAccum(float v, double* dst, float* red){
    v = warpRedSum(v);
    int w = threadIdx.x >> 5, ln = threadIdx.x & 31;
    if (ln == 0) red[w] = v;
    __syncthreads();
    if (threadIdx.x == 0){
        float s = 0.f;
        #pragma unroll
        for (int i=0;i<8;i++) s += red[i];
        atomicAdd(dst, (double)s);
    }
    __syncthreads();
}

// ------------------- zero stats -------------------
__global__ void K_zero(){
    int i = blockIdx.x*256 + threadIdx.x;
    if (i < 10*CC) g_stats[i] = 0.0;
}

// ------------------- depthwise 3x3, 3 branches + fused BN stats -------------------
// grid (2, C, B); block 256.
__global__ void K_dw(const float* __restrict__ x, const float* __restrict__ dw_w){
    __shared__ float im[66*128];
    __shared__ float red[8];
    int r0 = blockIdx.x*64, c = blockIdx.y, b = blockIdx.z;
    int tid = threadIdx.x;
    const float* xc = x + ((size_t)b*CC + c)*LL;
    #pragma unroll
    for (int i=0;i<33;i++){
        int e = i*256 + tid;
        int rr = e >> 7, w = e & 127;
        int gr = r0 - 1 + rr;
        im[e] = (gr >= 0 && gr < 128) ? xc[gr*128 + w] : 0.0f;
    }
    float wq[9], wk[9], wv[9];
    #pragma unroll
    for (int k=0;k<9;k++){
        wq[k] = dw_w[c*9 + k];
        wk[k] = dw_w[(CC   + c)*9 + k];
        wv[k] = dw_w[(2*CC + c)*9 + k];
    }
    __syncthreads();
    float sq=0.f, sq2=0.f, sk=0.f, sk2=0.f, sv=0.f, sv2=0.f;
    float* outq = g_dwq + ((size_t)b*CC + c)*LL + r0*128;
    #pragma unroll 2
    for (int i=0;i<32;i++){
        int s = i*256 + tid;
        int hl = s >> 7, w = s & 127;
        float acc = 0.f;
        #pragma unroll
        for (int ky=0;ky<3;ky++){
            const float* row = im + (hl+ky)*128 + w;
            if (w > 0)   acc += wq[ky*3+0] * row[-1];
                         acc += wq[ky*3+1] * row[0];
            if (w < 127) acc += wq[ky*3+2] * row[1];
        }
        outq[s] = acc;
        sq += acc; sq2 += acc*acc;
    }
    float* outk = g_dwk + ((size_t)b*CC + c)*LK + (r0>>1)*64;
    float* outv = g_dwv + ((size_t)b*CC + c)*LK + (r0>>1)*64;
    #pragma unroll
    for (int i=0;i<8;i++){
        int s = i*256 + tid;
        int ho = s >> 6, wo = s & 63;
        float ak = 0.f, av = 0.f;
        #pragma unroll
        for (int ky=0;ky<3;ky++){
            const float* row = im + (2*ho+ky)*128 + 2*wo;
            if (wo > 0){ ak += wk[ky*3+0]*row[-1]; av += wv[ky*3+0]*row[-1]; }
            ak += wk[ky*3+1]*row[0]; av += wv[ky*3+1]*row[0];
            ak += wk[ky*3+2]*row[1]; av += wv[ky*3+2]*row[1];
        }
        outk[s] = ak; outv[s] = av;
        sk += ak; sk2 += ak*ak; sv += av; sv2 += av*av;
    }
    __syncthreads();
    blockAccum(sq,  &g_stats[0*CC + c], red);
    blockAccum(sq2, &g_stats[1*CC + c], red);
    blockAccum(sk,  &g_stats[2*CC + c], red);
    blockAccum(sk2, &g_stats[3*CC + c], red);
    blockAccum(sv,  &g_stats[4*CC + c], red);
    blockAccum(sv2, &g_stats[5*CC + c], red);
}

// ------------------- fold BN2d into pointwise weights -------------------
__global__ void K_prep(const float* __restrict__ bn2_g, const float* __restrict__ bn2_b,
                       const float* __restrict__ pw_w, const float* __restrict__ pw_b){
    __shared__ float alpha[CC], beta[CC];
    int t = threadIdx.x;  // 128
    for (int i=0;i<3;i++){
        double cnt = (i==0) ? (double)BB*(double)LL : (double)BB*(double)LK;
        double m = g_stats[(size_t)(2*i)*CC + t] / cnt;
        double v = g_stats[(size_t)(2*i+1)*CC + t] / cnt - m*m;
        float A = bn2_g[i*CC + t] * rsqrtf((float)v + 1e-5f);
        alpha[t] = A;
        beta[t]  = bn2_b[i*CC + t] - (float)m * A;
        __syncthreads();
        float acc = pw_b[i*CC + t];
        const float* wrow = pw_w   + (size_t)(i*CC + t)*CC;
        float*      werow = g_weff + (size_t)(i*CC + t)*CC;
        for (int c2=0;c2<CC;c2++){
            float w = wrow[c2];
            werow[c2] = w * alpha[c2];
            acc += w * beta[c2];
        }
        g_beff[i*CC + t] = acc;
        __syncthreads();
    }
}

// ------------------- shared 128x128 GEMM mainloop (pack-free f32x2) -------------------
// block tile: 128 outs x 128 cols, 256 threads, microtile 8x8.
// acc[i][j]: output pair (ty*8+2i, ty*8+2i+1) at column tx*8+j.
// Xs2 holds each x value DUPLICATED (broadcast pairs) so no movs in inner loop.
#define WSM_FLOATS (32*132)
#define XS2_FLOATS (32*256)
__device__ __forceinline__ void gemm128(const float* __restrict__ W,
                                        const float* __restrict__ srcb, int Ls,
                                        float* Wsm, float* Xs2, ull acc[4][8]){
    int tid = threadIdx.x, tx = tid & 15, ty = tid >> 4;
    for (int k0=0;k0<128;k0+=32){
        __syncthreads();
        #pragma unroll
        for (int i=0;i<16;i++){
            int e = i*256 + tid;
            int o = e >> 5, kk = e & 31;
            Wsm[kk*132 + o] = W[o*128 + k0 + kk];
        }
        #pragma unroll
        for (int i=0;i<16;i++){
            int e = i*256 + tid;
            float v = srcb[(size_t)(k0 + (e>>7))*Ls + (e & 127)];
            *(ull*)&Xs2[(e>>7)*256 + (e&127)*2] = pack2(v, v);
        }
        __syncthreads();
        #pragma unroll
        for (int kk=0;kk<32;kk++){
            const ulonglong2* wr = (const ulonglong2*)&Wsm[kk*132 + ty*8];
            ulonglong2 wa = wr[0], wb = wr[1];
            ull w[4] = {wa.x, wa.y, wb.x, wb.y};
            const ulonglong2* xr = (const ulonglong2*)&Xs2[kk*256 + tx*16];
            ulonglong2 x0 = xr[0], x1 = xr[1], x2 = xr[2], x3 = xr[3];
            ull xb[8] = {x0.x, x0.y, x1.x, x1.y, x2.x, x2.y, x3.x, x3.y};
            #pragma unroll
            for (int i=0;i<4;i++)
                #pragma unroll
                for (int j=0;j<8;j++)
                    acc[i][j] = fma2(w[i], xb[j], acc[i][j]);
        }
    }
}

// ------------------- pointwise GEMM for k AND v + bias + GELU -------------------
// grid (LK/128, B, 2); dynamic smem.
__global__ void __launch_bounds__(256,2) K_pwkv(){
    extern __shared__ float dsm[];
    float* Wsm = dsm;
    float* Xs2 = dsm + WSM_FLOATS;
    int which = blockIdx.z + 1;
    const float* src  = (which==1) ? g_dwk : g_dwv;
    float*       dst  = (which==1) ? g_k   : g_v;
    const float* W    = g_weff + which*CC*CC;
    const float* bias = g_beff + which*CC;
    int b = blockIdx.y, l0 = blockIdx.x*128;
    ull acc[4][8];
    #pragma unroll
    for (int i=0;i<4;i++)
        #pragma unroll
        for (int j=0;j<8;j++) acc[i][j] = 0ULL;
    gemm128(W, src + ((size_t)b*CC)*LK + l0, LK, Wsm, Xs2, acc);
    int tid = threadIdx.x, tx = tid & 15, ty = tid >> 4;
    float* dstb = dst + ((size_t)b*CC)*LK + l0;
    #pragma unroll
    for (int i=0;i<4;i++){
        int oL = ty*8 + 2*i, oH = oL + 1;
        float bL = bias[oL], bH = bias[oH];
        float lo[8], hi[8];
        #pragma unroll
        for (int j=0;j<8;j++) unpack2(acc[i][j], lo[j], hi[j]);
        float4 r0, r1;
        r0.x = geluf(lo[0]+bL); r0.y = geluf(lo[1]+bL); r0.z = geluf(lo[2]+bL); r0.w = geluf(lo[3]+bL);
        r1.x = geluf(lo[4]+bL); r1.y = geluf(lo[5]+bL); r1.z = geluf(lo[6]+bL); r1.w = geluf(lo[7]+bL);
        *(float4*)&dstb[(size_t)oL*LK + tx*8]     = r0;
        *(float4*)&dstb[(size_t)oL*LK + tx*8 + 4] = r1;
        r0.x = geluf(hi[0]+bH); r0.y = geluf(hi[1]+bH); r0.z = geluf(hi[2]+bH); r0.w = geluf(hi[3]+bH);
        r1.x = geluf(hi[4]+bH); r1.y = geluf(hi[5]+bH); r1.z = geluf(hi[6]+bH); r1.w = geluf(hi[7]+bH);
        *(float4*)&dstb[(size_t)oH*LK + tx*8]     = r0;
        *(float4*)&dstb[(size_t)oH*LK + tx*8 + 4] = r1;
    }
}

// ------------------- per-row max + sum(exp) of k -------------------
// grid (B*C); block 256.
__global__ void K_krow(){
    int row = blockIdx.x;
    const float* p = g_k + (size_t)row*LK;
    int tid = threadIdx.x, w = tid >> 5, ln = tid & 31;
    float vals[16], m = -1e30f;
    #pragma unroll
    for (int i=0;i<16;i++){ vals[i] = p[i*256 + tid]; m = fmaxf(m, vals[i]); }
    #pragma unroll
    for (int o=16;o>0;o>>=1) m = fmaxf(m, __shfl_xor_sync(0xffffffffu, m, o));
    __shared__ float rm[8], rs[8];
    if (ln == 0) rm[w] = m;
    __syncthreads();
    float bm = rm[0];
    #pragma unroll
    for (int i=1;i<8;i++) bm = fmaxf(bm, rm[i]);
    float s = 0.f;
    #pragma unroll
    for (int i=0;i<16;i++) s += __expf(vals[i] - bm);
    s = warpRedSum(s);
    if (ln == 0) rs[w] = s;
    __syncthreads();
    if (tid == 0){
        float tot = 0.f;
        #pragma unroll
        for (int i=0;i<8;i++) tot += rs[i];
        g_km[row]  = bm;
        g_kis[row] = 1.f / tot;
    }
}

// ------------------- kv = softmax_n(k)^T @ v per (b,h) -------------------
// grid (B*H); block 256.
__global__ void K_kv(){
    __shared__ float ks[16*257], vs[16*257];
    __shared__ float mrow[16], isrow[16];
    int bh = blockIdx.x; int b = bh >> 3, h = bh & 7;
    int tid = threadIdx.x; int d = tid >> 4, e = tid & 15;
    const float* kb = g_k + ((size_t)b*CC + h*16)*LK;
    const float* vb = g_v + ((size_t)b*CC + h*16)*LK;
    if (tid < 16){
        mrow[tid]  = g_km [b*CC + h*16 + tid];
        isrow[tid] = g_kis[b*CC + h*16 + tid];
    }
    __syncthreads();
    float acc = 0.f;
    for (int n0=0;n0<LK;n0+=256){
        __syncthreads();
        #pragma unroll
        for (int i=0;i<16;i++){
            ks[i*257 + tid] = __expf(kb[(size_t)i*LK + n0 + tid] - mrow[i]) * isrow[i];
            vs[i*257 + tid] = vb[(size_t)i*LK + n0 + tid];
        }
        __syncthreads();
        #pragma unroll 8
        for (int j=0;j<256;j++)
            acc += ks[d*257 + j] * vs[e*257 + j];
    }
    g_kv[((size_t)bh*16 + d)*16 + e] = acc;
}

// ------------------- q GEMM + GELU + attention + residual + z-stats -------------------
// grid (LL/128, B); block 256; dynamic smem.
__global__ void __launch_bounds__(256,2) K_pwatt(const float* __restrict__ x, const float* __restrict__ add_w){
    extern __shared__ float dsm[];
    float* Wsm = dsm;                 // 4224 floats
    float* Xs2 = dsm + WSM_FLOATS;    // 8192 floats
    float* Qs  = dsm;                 // 128*132 = 16896 floats (reuses gemm region)
    float* kvs = dsm + 16896;         // 2048 floats
    int tid = threadIdx.x;
    int b = blockIdx.y, l0 = blockIdx.x*128;
    {
        const float* kvp = g_kv + (size_t)b*NH*DH*DH;
        for (int i=tid;i<NH*DH*DH;i+=256) kvs[i] = kvp[i];
    }
    ull acc[4][8];
    #pragma unroll
    for (int i=0;i<4;i++)
        #pragma unroll
        for (int j=0;j<8;j++) acc[i][j] = 0ULL;
    gemm128(g_weff, g_dwq + ((size_t)b*CC)*LL + l0, LL, Wsm, Xs2, acc);
    __syncthreads();
    int tx = tid & 15, ty = tid >> 4;
    #pragma unroll
    for (int i=0;i<4;i++){
        int oL = ty*8 + 2*i, oH = oL + 1;
        float bL = g_beff[oL], bH = g_beff[oH];
        float lo[8], hi[8];
        #pragma unroll
        for (int j=0;j<8;j++) unpack2(acc[i][j], lo[j], hi[j]);
        float4 r0, r1;
        r0.x = geluf(lo[0]+bL); r0.y = geluf(lo[1]+bL); r0.z = geluf(lo[2]+bL); r0.w = geluf(lo[3]+bL);
        r1.x = geluf(lo[4]+bL); r1.y = geluf(lo[5]+bL); r1.z = geluf(lo[6]+bL); r1.w = geluf(lo[7]+bL);
        *(float4*)&Qs[oL*132 + tx*8]     = r0;
        *(float4*)&Qs[oL*132 + tx*8 + 4] = r1;
        r0.x = geluf(hi[0]+bH); r0.y = geluf(hi[1]+bH); r0.z = geluf(hi[2]+bH); r0.w = geluf(hi[3]+bH);
        r1.x = geluf(hi[4]+bH); r1.y = geluf(hi[5]+bH); r1.z = geluf(hi[6]+bH); r1.w = geluf(hi[7]+bH);
        *(float4*)&Qs[oH*132 + tx*8]     = r0;
        *(float4*)&Qs[oH*132 + tx*8 + 4] = r1;
    }
    __syncthreads();
    // attention: thread handles token l for 4 heads
    {
        int l = tid & 127, hb = (tid >> 7) * 4;
        #pragma unroll
        for (int hh=0;hh<4;hh++){
            int h = hb + hh;
            float qv[16], m = -1e30f;
            #pragma unroll
            for (int d=0;d<16;d++){ qv[d] = Qs[(h*16+d)*132 + l]; m = fmaxf(m, qv[d]); }
            float s = 0.f;
            #pragma unroll
            for (int d=0;d<16;d++){ qv[d] = __expf(qv[d] - m); s += qv[d]; }
            float is = 1.f / s;
            const float* kvh = kvs + h*256;
            float av[16];
            #pragma unroll
            for (int e=0;e<16;e++) av[e] = 0.f;
            #pragma unroll
            for (int d=0;d<16;d++){
                float q = qv[d];
                #pragma unroll
                for (int e=0;e<16;e++) av[e] += q * kvh[d*16 + e];
            }
            #pragma unroll
            for (int e=0;e<16;e++) Qs[(h*16+e)*132 + l] = av[e] * is;
        }
    }
    __syncthreads();
    // residual addw + writeout + store z into Qs for stats
    float a0 = fmaxf(add_w[0], 0.f), a1 = fmaxf(add_w[1], 0.f);
    float inv = 1.f / (a0 + a1 + 1e-12f);
    float w0 = a0*inv, w1 = a1*inv;
    const float* xb = x   + ((size_t)b*CC)*LL + l0;
    float*       zb = g_z + ((size_t)b*CC)*LL + l0;
    #pragma unroll 4
    for (int i=0;i<64;i++){
        int e = i*256 + tid;
        int c = e >> 7, lc = e & 127;
        float att = Qs[c*132 + lc];
        float zv = w0*att + w1*xb[(size_t)c*LL + lc];
        zb[(size_t)c*LL + lc] = zv;
        Qs[c*132 + lc] = zv;
    }
    __syncthreads();
    if (tid < 128){
        float s = 0.f, s2 = 0.f;
        #pragma unroll 8
        for (int j=0;j<128;j++){ float v = Qs[tid*132 + j]; s += v; s2 += v*v; }
        atomicAdd(&g_stats[6*CC + tid], (double)s);
        atomicAdd(&g_stats[7*CC + tid], (double)s2);
    }
}

// ------------------- BN1d affine coefficients -------------------
__global__ void K_bnaff(int sel, const float* __restrict__ g, const float* __restrict__ bt){
    int t = threadIdx.x;
    int slot = sel ? 8 : 6;
    double cnt = (double)BB * (double)LL;
    double m = g_stats[(size_t)slot*CC + t] / cnt;
    double v = g_stats[(size_t)(slot+1)*CC + t] / cnt - m*m;
    float a = g[t] * rsqrtf((float)v + 1e-5f);
    float bc = bt[t] - (float)m * a;
    if (sel){ g_A2[t] = a; g_B2[t] = bc; }
    else    { g_A1[t] = a; g_B1[t] = bc; }
}

// ------------------- FFN (128->32->128) f32x2 + residual addw -> g_pre -------------------
// grid (LL/256, B); block 256; one token per thread.
__global__ void __launch_bounds__(256,2) K_ffn(const float* __restrict__ W1, const float* __restrict__ b1,
                      const float* __restrict__ W2, const float* __restrict__ b2,
                      const float* __restrict__ fw){
    __shared__ __align__(16) float W1s[128*32];
    __shared__ __align__(16) float W2s[32*128];
    __shared__ float b1s[32], b2s[128], sA[128], sB[128];
    int tid = threadIdx.x;
    int b = blockIdx.y;
    int l = blockIdx.x*256 + tid;
    #pragma unroll
    for (int i=0;i<16;i++){ W1s[i*256 + tid] = W1[i*256 + tid]; W2s[i*256 + tid] = W2[i*256 + tid]; }
    if (tid < 32) b1s[tid] = b1[tid];
    if (tid < 128){ b2s[tid] = b2[tid]; sA[tid] = g_A1[tid]; sB[tid] = g_B1[tid]; }
    __syncthreads();
    float a0 = fmaxf(fw[0], 0.f), a1 = fmaxf(fw[1], 0.f);
    float inv = 1.f / (a0 + a1 + 1e-12f);
    float w0 = a0*inv, w1 = a1*inv;
    const float* zb = g_z   + ((size_t)b*CC)*LL + l;
    float*       pb = g_pre + ((size_t)b*CC)*LL + l;
    // phase A: h = W1^T xin + b1 (packed over f pairs)
    ull hp[16];
    #pragma unroll
    for (int j=0;j<16;j++) hp[j] = pack2(b1s[2*j], b1s[2*j+1]);
    for (int c=0;c<128;c++){
        float xv = sA[c]*zb[(size_t)c*LL] + sB[c];
        ull xp = pack2(xv, xv);
        const ull* wr = (const ull*)&W1s[c*32];
        #pragma unroll
        for (int j=0;j<16;j++) hp[j] = fma2(wr[j], xp, hp[j]);
    }
    // gelu + broadcast-pack
    ull hbp[32];
    #pragma unroll
    for (int j=0;j<16;j++){
        float ha, hb2;
        unpack2(hp[j], ha, hb2);
        ha = geluf(ha); hb2 = geluf(hb2);
        hbp[2*j]   = pack2(ha, ha);
        hbp[2*j+1] = pack2(hb2, hb2);
    }
    // phase B: out = W2^T h + b2 (packed over o pairs), 8 outs at a time
    for (int og=0;og<16;og++){
        int o0 = og*8;
        ull a0p = pack2(b2s[o0],   b2s[o0+1]);
        ull a1p = pack2(b2s[o0+2], b2s[o0+3]);
        ull a2p = pack2(b2s[o0+4], b2s[o0+5]);
        ull a3p = pack2(b2s[o0+6], b2s[o0+7]);
        #pragma unroll
        for (int f=0;f<32;f++){
            const ulonglong2* wr = (const ulonglong2*)&W2s[f*128 + o0];
            ulonglong2 wa = wr[0], wb = wr[1];
            a0p = fma2(wa.x, hbp[f], a0p);
            a1p = fma2(wa.y, hbp[f], a1p);
            a2p = fma2(wb.x, hbp[f], a2p);
            a3p = fma2(wb.y, hbp[f], a3p);
        }
        float y[8];
        unpack2(a0p, y[0], y[1]);
        unpack2(a1p, y[2], y[3]);
        unpack2(a2p, y[4], y[5]);
        unpack2(a3p, y[6], y[7]);
        #pragma unroll
        for (int j=0;j<8;j++){
            int o = o0 + j;
            float yv = geluf(y[j]);
            float ao = sA[o]*zb[(size_t)o*LL] + sB[o];
            pb[(size_t)o*LL] = w0*yv + w1*ao;
        }
    }
}

// ------------------- stats for g_pre -------------------
// grid (C, 64); block 256.
__global__ void K_statsP(){
    int c = blockIdx.x, j = blockIdx.y;
    int b = j >> 2, lq = j & 3;
    const float* p = g_pre + ((size_t)b*CC + c)*LL + lq*4096;
    int tid = threadIdx.x;
    float s = 0.f, s2 = 0.f;
    #pragma unroll
    for (int i=0;i<16;i++){ float v = p[i*256 + tid]; s += v; s2 += v*v; }
    s = warpRedSum(s); s2 = warpRedSum(s2);
    __shared__ float r1[8], r2[8];
    int w = tid >> 5, ln = tid & 31;
    if (ln == 0){ r1[w] = s; r2[w] = s2; }
    __syncthreads();
    if (tid == 0){
        float a = 0.f, bq = 0.f;
        #pragma unroll
        for (int i=0;i<8;i++){ a += r1[i]; bq += r2[i]; }
        atomicAdd(&g_stats[8*CC + c], (double)a);
        atomicAdd(&g_stats[9*CC + c], (double)bq);
    }
}

// ------------------- final BN affine -> d_out -------------------
__global__ void K_final(float* __restrict__ out){
    size_t i = ((size_t)blockIdx.x*256 + threadIdx.x)*4;
    int c = (int)((i >> 14) & 127);
    float4 v = *(const float4*)&g_pre[i];
    float A = g_A2[c], Bc = g_B2[c];
    float4 r;
    r.x = A*v.x + Bc; r.y = A*v.y + Bc; r.z = A*v.z + Bc; r.w = A*v.w + Bc;
    *(float4*)&out[i] = r;
}

// ------------------- launch -------------------
extern "C" void kernel_launch(void* const* d_in, const int* in_sizes, int n_in,
                              void* d_out, int out_size){
    const float* x         = (const float*)d_in[0];
    const float* dw_w      = (const float*)d_in[1];
    const float* bn2_g     = (const float*)d_in[2];
    const float* bn2_b     = (const float*)d_in[3];
    const float* pw_w      = (const float*)d_in[4];
    const float* pw_b      = (const float*)d_in[5];
    const float* add_w     = (const float*)d_in[6];
    const float* bn1_g     = (const float*)d_in[7];
    const float* bn1_b     = (const float*)d_in[8];
    const float* W1        = (const float*)d_in[9];
    const float* b1        = (const float*)d_in[10];
    const float* W2        = (const float*)d_in[11];
    const float* b2        = (const float*)d_in[12];
    const float* ffn_add_w = (const float*)d_in[13];
    const float* ffn_bn_g  = (const float*)d_in[14];
    const float* ffn_bn_b  = (const float*)d_in[15];
    float* out = (float*)d_out;

    const int GEMM_SMEM  = (WSM_FLOATS + XS2_FLOATS) * 4;   // 49664 bytes
    const int PWATT_SMEM = (16896 + 2048) * 4;              // 75776 bytes
    cudaFuncSetAttribute(K_pwkv,  cudaFuncAttributeMaxDynamicSharedMemorySize, GEMM_SMEM);
    cudaFuncSetAttribute(K_pwatt, cudaFuncAttributeMaxDynamicSharedMemorySize, PWATT_SMEM);

    K_zero<<<5,256>>>();
    K_dw<<<dim3(2,CC,BB),256>>>(x, dw_w);
    K_prep<<<1,128>>>(bn2_g, bn2_b, pw_w, pw_b);
    K_pwkv<<<dim3(LK/128,BB,2),256,GEMM_SMEM>>>();
    K_krow<<<BB*CC,256>>>();
    K_kv<<<BB*NH,256>>>();
    K_pwatt<<<dim3(LL/128,BB),256,PWATT_SMEM>>>(x, add_w);
    K_bnaff<<<1,128>>>(0, bn1_g, bn1_b);
    K_ffn<<<dim3(LL/256,BB),256>>>(W1, b1, W2, b2, ffn_add_w);
    K_statsP<<<dim3(CC,64),256>>>();
    K_bnaff<<<1,128>>>(1, ffn_bn_g, ffn_bn_b);
    K_final<<<(BB*CC*LL)/(256*4),256>>>(out);
}

// round 11
// speedup vs baseline: 1.5183x; 1.5183x over previous
#include <cuda_runtime.h>
#include <math.h>

#define BB 16
#define CC 128
#define LL 16384
#define LK 4096
#define NH 8
#define DH 16

typedef unsigned long long ull;

// ------------------- scratch (device globals; no allocations) -------------------
__device__ float g_dwq[BB*CC*LL];
__device__ float g_dwk[BB*CC*LK];
__device__ float g_dwv[BB*CC*LK];
__device__ float g_k  [BB*CC*LK];
__device__ float g_v  [BB*CC*LK];
__device__ float g_z  [BB*CC*LL];
__device__ float g_pre[BB*CC*LL];
__device__ float g_kv [BB*NH*DH*DH];
__device__ float g_km [BB*CC];
__device__ float g_kis[BB*CC];
__device__ float g_weff[3*CC*CC];
__device__ float g_beff[3*CC];
__device__ float g_A1[CC], g_B1[CC], g_A2[CC], g_B2[CC];
// slots: 0/1 dwq, 2/3 dwk, 4/5 dwv, 6/7 z, 8/9 pre
__device__ double g_stats[10*CC];

// ------------------- helpers -------------------
__device__ __forceinline__ float geluf(float x){
    return 0.5f * x * (1.0f + erff(x * 0.70710678118654752440f));
}
__device__ __forceinline__ float warpRedSum(float v){
    v += __shfl_xor_sync(0xffffffffu, v, 16);
    v += __shfl_xor_sync(0xffffffffu, v, 8);
    v += __shfl_xor_sync(0xffffffffu, v, 4);
    v += __shfl_xor_sync(0xffffffffu, v, 2);
    v += __shfl_xor_sync(0xffffffffu, v, 1);
    return v;
}
__device__ __forceinline__ ull pack2(float lo, float hi){
    ull r; unsigned a = __float_as_uint(lo), b = __float_as_uint(hi);
    asm("mov.b64 %0, {%1,%2};" : "=l"(r) : "r"(a), "r"(b));
    return r;
}
__device__ __forceinline__ void unpack2(ull v, float& lo, float& hi){
    unsigned a, b;
    asm("mov.b64 {%0,%1}, %2;" : "=r"(a), "=r"(b) : "l"(v));
    lo = __uint_as_float(a); hi = __uint_as_float(b);
}
__device__ __forceinline__ ull fma2(ull a, ull b, ull c){
    ull d;
    asm("fma.rn.f32x2 %0, %1, %2, %3;" : "=l"(d) : "l"(a), "l"(b), "l"(c));
    return d;
}

__device__ __forceinline__ void blockAccum(float v, double* dst, float* red){
    v = warpRedSum(v);
    int w = threadIdx.x >> 5, ln = threadIdx.x & 31;
    if (ln == 0) red[w] = v;
    __syncthreads();
    if (threadIdx.x == 0){
        float s = 0.f;
        #pragma unroll
        for (int i=0;i<8;i++) s += red[i];
        atomicAdd(dst, (double)s);
    }
    __syncthreads();
}

// ------------------- zero stats -------------------
__global__ void K_zero(){
    int i = blockIdx.x*256 + threadIdx.x;
    if (i < 10*CC) g_stats[i] = 0.0;
}

// ------------------- depthwise 3x3, 3 branches + fused BN stats -------------------
// grid (2, C, B); block 256.
__global__ void K_dw(const float* __restrict__ x, const float* __restrict__ dw_w){
    __shared__ float im[66*128];
    __shared__ float red[8];
    int r0 = blockIdx.x*64, c = blockIdx.y, b = blockIdx.z;
    int tid = threadIdx.x;
    const float* xc = x + ((size_t)b*CC + c)*LL;
    #pragma unroll
    for (int i=0;i<33;i++){
        int e = i*256 + tid;
        int rr = e >> 7, w = e & 127;
        int gr = r0 - 1 + rr;
        im[e] = (gr >= 0 && gr < 128) ? xc[gr*128 + w] : 0.0f;
    }
    float wq[9], wk[9], wv[9];
    #pragma unroll
    for (int k=0;k<9;k++){
        wq[k] = dw_w[c*9 + k];
        wk[k] = dw_w[(CC   + c)*9 + k];
        wv[k] = dw_w[(2*CC + c)*9 + k];
    }
    __syncthreads();
    float sq=0.f, sq2=0.f, sk=0.f, sk2=0.f, sv=0.f, sv2=0.f;
    float* outq = g_dwq + ((size_t)b*CC + c)*LL + r0*128;
    #pragma unroll 2
    for (int i=0;i<32;i++){
        int s = i*256 + tid;
        int hl = s >> 7, w = s & 127;
        float acc = 0.f;
        #pragma unroll
        for (int ky=0;ky<3;ky++){
            const float* row = im + (hl+ky)*128 + w;
            if (w > 0)   acc += wq[ky*3+0] * row[-1];
                         acc += wq[ky*3+1] * row[0];
            if (w < 127) acc += wq[ky*3+2] * row[1];
        }
        outq[s] = acc;
        sq += acc; sq2 += acc*acc;
    }
    float* outk = g_dwk + ((size_t)b*CC + c)*LK + (r0>>1)*64;
    float* outv = g_dwv + ((size_t)b*CC + c)*LK + (r0>>1)*64;
    #pragma unroll
    for (int i=0;i<8;i++){
        int s = i*256 + tid;
        int ho = s >> 6, wo = s & 63;
        float ak = 0.f, av = 0.f;
        #pragma unroll
        for (int ky=0;ky<3;ky++){
            const float* row = im + (2*ho+ky)*128 + 2*wo;
            if (wo > 0){ ak += wk[ky*3+0]*row[-1]; av += wv[ky*3+0]*row[-1]; }
            ak += wk[ky*3+1]*row[0]; av += wv[ky*3+1]*row[0];
            ak += wk[ky*3+2]*row[1]; av += wv[ky*3+2]*row[1];
        }
        outk[s] = ak; outv[s] = av;
        sk += ak; sk2 += ak*ak; sv += av; sv2 += av*av;
    }
    __syncthreads();
    blockAccum(sq,  &g_stats[0*CC + c], red);
    blockAccum(sq2, &g_stats[1*CC + c], red);
    blockAccum(sk,  &g_stats[2*CC + c], red);
    blockAccum(sk2, &g_stats[3*CC + c], red);
    blockAccum(sv,  &g_stats[4*CC + c], red);
    blockAccum(sv2, &g_stats[5*CC + c], red);
}

// ------------------- fold BN2d into pointwise weights -------------------
__global__ void K_prep(const float* __restrict__ bn2_g, const float* __restrict__ bn2_b,
                       const float* __restrict__ pw_w, const float* __restrict__ pw_b){
    __shared__ float alpha[CC], beta[CC];
    int t = threadIdx.x;  // 128
    for (int i=0;i<3;i++){
        double cnt = (i==0) ? (double)BB*(double)LL : (double)BB*(double)LK;
        double m = g_stats[(size_t)(2*i)*CC + t] / cnt;
        double v = g_stats[(size_t)(2*i+1)*CC + t] / cnt - m*m;
        float A = bn2_g[i*CC + t] * rsqrtf((float)v + 1e-5f);
        alpha[t] = A;
        beta[t]  = bn2_b[i*CC + t] - (float)m * A;
        __syncthreads();
        float acc = pw_b[i*CC + t];
        const float* wrow = pw_w   + (size_t)(i*CC + t)*CC;
        float*      werow = g_weff + (size_t)(i*CC + t)*CC;
        for (int c2=0;c2<CC;c2++){
            float w = wrow[c2];
            werow[c2] = w * alpha[c2];
            acc += w * beta[c2];
        }
        g_beff[i*CC + t] = acc;
        __syncthreads();
    }
}

// ------------------- shared GEMM mainloop: 128 outs x 64 cols, 128 threads -------------------
// microtile 8x8 per thread; ty = tid>>3 (0..15 row-group), tx = tid&7 (0..7 col-group).
// acc[i][j]: output row ty*8+i, column pair (tx*8+2j, tx*8+2j+1).
__device__ __forceinline__ void gemm64(const float* __restrict__ W,
                                       const float* __restrict__ srcb, int Ls,
                                       float* Wsm, float* Xs, ull acc[8][4]){
    int tid = threadIdx.x, tx = tid & 7, ty = tid >> 3;
    for (int k0=0;k0<128;k0+=32){
        __syncthreads();
        #pragma unroll
        for (int i=0;i<32;i++){
            int e = i*128 + tid;
            int o = e >> 5, kk = e & 31;
            Wsm[kk*132 + o] = W[o*128 + k0 + kk];
        }
        #pragma unroll
        for (int i=0;i<16;i++){
            int e = i*128 + tid;
            Xs[e] = srcb[(size_t)(k0 + (e>>6))*Ls + (e & 63)];
        }
        __syncthreads();
        #pragma unroll
        for (int kk=0;kk<32;kk++){
            const float* wr = &Wsm[kk*132 + ty*8];
            float4 w0 = *(const float4*)wr;
            float4 w1 = *(const float4*)(wr + 4);
            ull wp[8] = { pack2(w0.x,w0.x), pack2(w0.y,w0.y), pack2(w0.z,w0.z), pack2(w0.w,w0.w),
                          pack2(w1.x,w1.x), pack2(w1.y,w1.y), pack2(w1.z,w1.z), pack2(w1.w,w1.w) };
            const ulonglong2* xr = (const ulonglong2*)&Xs[kk*64 + tx*8];
            ulonglong2 xa = xr[0], xb = xr[1];
            #pragma unroll
            for (int i=0;i<8;i++){
                acc[i][0] = fma2(wp[i], xa.x, acc[i][0]);
                acc[i][1] = fma2(wp[i], xa.y, acc[i][1]);
                acc[i][2] = fma2(wp[i], xb.x, acc[i][2]);
                acc[i][3] = fma2(wp[i], xb.y, acc[i][3]);
            }
        }
    }
}

// ------------------- pointwise GEMM for k AND v + bias + GELU -------------------
// grid (LK/64, B, 2); block 128.
__global__ void K_pwkv(){
    __shared__ __align__(16) float Wsm[32*132];
    __shared__ __align__(16) float Xs[32*64];
    int which = blockIdx.z + 1;
    const float* src  = (which==1) ? g_dwk : g_dwv;
    float*       dst  = (which==1) ? g_k   : g_v;
    const float* W    = g_weff + which*CC*CC;
    const float* bias = g_beff + which*CC;
    int b = blockIdx.y, l0 = blockIdx.x*64;
    ull acc[8][4];
    #pragma unroll
    for (int i=0;i<8;i++)
        #pragma unroll
        for (int j=0;j<4;j++) acc[i][j] = 0ULL;
    gemm64(W, src + ((size_t)b*CC)*LK + l0, LK, Wsm, Xs, acc);
    int tid = threadIdx.x, tx = tid & 7, ty = tid >> 3;
    float* dstb = dst + ((size_t)b*CC)*LK + l0;
    #pragma unroll
    for (int i=0;i<8;i++){
        int o = ty*8 + i;
        float bv = bias[o];
        float v[8];
        unpack2(acc[i][0], v[0], v[1]);
        unpack2(acc[i][1], v[2], v[3]);
        unpack2(acc[i][2], v[4], v[5]);
        unpack2(acc[i][3], v[6], v[7]);
        float4 r0, r1;
        r0.x = geluf(v[0]+bv); r0.y = geluf(v[1]+bv); r0.z = geluf(v[2]+bv); r0.w = geluf(v[3]+bv);
        r1.x = geluf(v[4]+bv); r1.y = geluf(v[5]+bv); r1.z = geluf(v[6]+bv); r1.w = geluf(v[7]+bv);
        *(float4*)&dstb[(size_t)o*LK + tx*8]     = r0;
        *(float4*)&dstb[(size_t)o*LK + tx*8 + 4] = r1;
    }
}

// ------------------- per-row max + sum(exp) of k -------------------
// grid (B*C); block 256.
__global__ void K_krow(){
    int row = blockIdx.x;
    const float* p = g_k + (size_t)row*LK;
    int tid = threadIdx.x, w = tid >> 5, ln = tid & 31;
    float vals[16], m = -1e30f;
    #pragma unroll
    for (int i=0;i<16;i++){ vals[i] = p[i*256 + tid]; m = fmaxf(m, vals[i]); }
    #pragma unroll
    for (int o=16;o>0;o>>=1) m = fmaxf(m, __shfl_xor_sync(0xffffffffu, m, o));
    __shared__ float rm[8], rs[8];
    if (ln == 0) rm[w] = m;
    __syncthreads();
    float bm = rm[0];
    #pragma unroll
    for (int i=1;i<8;i++) bm = fmaxf(bm, rm[i]);
    float s = 0.f;
    #pragma unroll
    for (int i=0;i<16;i++) s += __expf(vals[i] - bm);
    s = warpRedSum(s);
    if (ln == 0) rs[w] = s;
    __syncthreads();
    if (tid == 0){
        float tot = 0.f;
        #pragma unroll
        for (int i=0;i<8;i++) tot += rs[i];
        g_km[row]  = bm;
        g_kis[row] = 1.f / tot;
    }
}

// ------------------- kv = softmax_n(k)^T @ v per (b,h) -------------------
// grid (B*H); block 256.
__global__ void K_kv(){
    __shared__ float ks[16*257], vs[16*257];
    __shared__ float mrow[16], isrow[16];
    int bh = blockIdx.x; int b = bh >> 3, h = bh & 7;
    int tid = threadIdx.x; int d = tid >> 4, e = tid & 15;
    const float* kb = g_k + ((size_t)b*CC + h*16)*LK;
    const float* vb = g_v + ((size_t)b*CC + h*16)*LK;
    if (tid < 16){
        mrow[tid]  = g_km [b*CC + h*16 + tid];
        isrow[tid] = g_kis[b*CC + h*16 + tid];
    }
    __syncthreads();
    float acc = 0.f;
    for (int n0=0;n0<LK;n0+=256){
        __syncthreads();
        #pragma unroll
        for (int i=0;i<16;i++){
            ks[i*257 + tid] = __expf(kb[(size_t)i*LK + n0 + tid] - mrow[i]) * isrow[i];
            vs[i*257 + tid] = vb[(size_t)i*LK + n0 + tid];
        }
        __syncthreads();
        #pragma unroll 8
        for (int j=0;j<256;j++)
            acc += ks[d*257 + j] * vs[e*257 + j];
    }
    g_kv[((size_t)bh*16 + d)*16 + e] = acc;
}

// ------------------- q GEMM + GELU + attention + residual + z-stats -------------------
// grid (LL/64, B); block 128. Qs stride 68; kvs after Qs (gemm region only 6272 floats).
__global__ void K_pwatt(const float* __restrict__ x, const float* __restrict__ add_w){
    __shared__ __align__(16) float dsm[128*68 + 2048];
    float* Wsm = dsm;            // 4224 floats (gemm phase)
    float* Xs  = dsm + 4224;     // 2048 floats (gemm phase)
    float* Qs  = dsm;            // 128*68 = 8704 floats (post-gemm)
    float* kvs = dsm + 128*68;   // 2048 floats (persistent)
    int tid = threadIdx.x;
    int b = blockIdx.y, l0 = blockIdx.x*64;
    {
        const float* kvp = g_kv + (size_t)b*NH*DH*DH;
        for (int i=tid;i<NH*DH*DH;i+=128) kvs[i] = kvp[i];
    }
    ull acc[8][4];
    #pragma unroll
    for (int i=0;i<8;i++)
        #pragma unroll
        for (int j=0;j<4;j++) acc[i][j] = 0ULL;
    gemm64(g_weff, g_dwq + ((size_t)b*CC)*LL + l0, LL, Wsm, Xs, acc);
    __syncthreads();
    int tx = tid & 7, ty = tid >> 3;
    #pragma unroll
    for (int i=0;i<8;i++){
        int o = ty*8 + i;
        float bv = g_beff[o];
        float v[8];
        unpack2(acc[i][0], v[0], v[1]);
        unpack2(acc[i][1], v[2], v[3]);
        unpack2(acc[i][2], v[4], v[5]);
        unpack2(acc[i][3], v[6], v[7]);
        float4 r0, r1;
        r0.x = geluf(v[0]+bv); r0.y = geluf(v[1]+bv); r0.z = geluf(v[2]+bv); r0.w = geluf(v[3]+bv);
        r1.x = geluf(v[4]+bv); r1.y = geluf(v[5]+bv); r1.z = geluf(v[6]+bv); r1.w = geluf(v[7]+bv);
        *(float4*)&Qs[o*68 + tx*8]     = r0;
        *(float4*)&Qs[o*68 + tx*8 + 4] = r1;
    }
    __syncthreads();
    // attention: thread handles token l (64 tokens) for 4 heads
    {
        int l = tid & 63, hb = (tid >> 6) * 4;
        #pragma unroll
        for (int hh=0;hh<4;hh++){
            int h = hb + hh;
            float qv[16], m = -1e30f;
            #pragma unroll
            for (int d=0;d<16;d++){ qv[d] = Qs[(h*16+d)*68 + l]; m = fmaxf(m, qv[d]); }
            float s = 0.f;
            #pragma unroll
            for (int d=0;d<16;d++){ qv[d] = __expf(qv[d] - m); s += qv[d]; }
            float is = 1.f / s;
            const float* kvh = kvs + h*256;
            float av[16];
            #pragma unroll
            for (int e=0;e<16;e++) av[e] = 0.f;
            #pragma unroll
            for (int d=0;d<16;d++){
                float q = qv[d];
                #pragma unroll
                for (int e=0;e<16;e++) av[e] += q * kvh[d*16 + e];
            }
            #pragma unroll
            for (int e=0;e<16;e++) Qs[(h*16+e)*68 + l] = av[e] * is;
        }
    }
    __syncthreads();
    // residual addw + writeout + keep z in Qs for stats
    float a0 = fmaxf(add_w[0], 0.f), a1 = fmaxf(add_w[1], 0.f);
    float inv = 1.f / (a0 + a1 + 1e-12f);
    float w0 = a0*inv, w1 = a1*inv;
    const float* xb = x   + ((size_t)b*CC)*LL + l0;
    float*       zb = g_z + ((size_t)b*CC)*LL + l0;
    #pragma unroll 4
    for (int i=0;i<64;i++){
        int e = i*128 + tid;
        int c = e >> 6, lc = e & 63;
        float att = Qs[c*68 + lc];
        float zv = w0*att + w1*xb[(size_t)c*LL + lc];
        zb[(size_t)c*LL + lc] = zv;
        Qs[c*68 + lc] = zv;
    }
    __syncthreads();
    // per-channel partial stats (each of 128 threads owns one channel row)
    {
        float s = 0.f, s2 = 0.f;
        #pragma unroll 8
        for (int j=0;j<64;j++){ float v = Qs[tid*68 + j]; s += v; s2 += v*v; }
        atomicAdd(&g_stats[6*CC + tid], (double)s);
        atomicAdd(&g_stats[7*CC + tid], (double)s2);
    }
}

// ------------------- BN1d affine coefficients -------------------
__global__ void K_bnaff(int sel, const float* __restrict__ g, const float* __restrict__ bt){
    int t = threadIdx.x;
    int slot = sel ? 8 : 6;
    double cnt = (double)BB * (double)LL;
    double m = g_stats[(size_t)slot*CC + t] / cnt;
    double v = g_stats[(size_t)(slot+1)*CC + t] / cnt - m*m;
    float a = g[t] * rsqrtf((float)v + 1e-5f);
    float bc = bt[t] - (float)m * a;
    if (sel){ g_A2[t] = a; g_B2[t] = bc; }
    else    { g_A1[t] = a; g_B1[t] = bc; }
}

// ------------------- FFN (128->32->128) f32x2 + residual addw -> g_pre -------------------
// grid (LL/256, B); block 256; one token per thread. NO launch_bounds (avoid spills).
__global__ void K_ffn(const float* __restrict__ W1, const float* __restrict__ b1,
                      const float* __restrict__ W2, const float* __restrict__ b2,
                      const float* __restrict__ fw){
    __shared__ __align__(16) float W1s[128*32];
    __shared__ __align__(16) float W2s[32*128];
    __shared__ float b1s[32], b2s[128], sA[128], sB[128];
    int tid = threadIdx.x;
    int b = blockIdx.y;
    int l = blockIdx.x*256 + tid;
    #pragma unroll
    for (int i=0;i<16;i++){ W1s[i*256 + tid] = W1[i*256 + tid]; W2s[i*256 + tid] = W2[i*256 + tid]; }
    if (tid < 32) b1s[tid] = b1[tid];
    if (tid < 128){ b2s[tid] = b2[tid]; sA[tid] = g_A1[tid]; sB[tid] = g_B1[tid]; }
    __syncthreads();
    float a0 = fmaxf(fw[0], 0.f), a1 = fmaxf(fw[1], 0.f);
    float inv = 1.f / (a0 + a1 + 1e-12f);
    float w0 = a0*inv, w1 = a1*inv;
    const float* zb = g_z   + ((size_t)b*CC)*LL + l;
    float*       pb = g_pre + ((size_t)b*CC)*LL + l;
    // phase A: h = W1^T xin + b1 (packed over f pairs)
    ull hp[16];
    #pragma unroll
    for (int j=0;j<16;j++) hp[j] = pack2(b1s[2*j], b1s[2*j+1]);
    for (int c=0;c<128;c++){
        float xv = sA[c]*zb[(size_t)c*LL] + sB[c];
        ull xp = pack2(xv, xv);
        const ull* wr = (const ull*)&W1s[c*32];
        #pragma unroll
        for (int j=0;j<16;j++) hp[j] = fma2(wr[j], xp, hp[j]);
    }
    // gelu + broadcast-pack
    ull hbp[32];
    #pragma unroll
    for (int j=0;j<16;j++){
        float ha, hb2;
        unpack2(hp[j], ha, hb2);
        ha = geluf(ha); hb2 = geluf(hb2);
        hbp[2*j]   = pack2(ha, ha);
        hbp[2*j+1] = pack2(hb2, hb2);
    }
    // phase B: out = W2^T h + b2 (packed over o pairs), 8 outs at a time
    for (int og=0;og<16;og++){
        int o0 = og*8;
        ull a0p = pack2(b2s[o0],   b2s[o0+1]);
        ull a1p = pack2(b2s[o0+2], b2s[o0+3]);
        ull a2p = pack2(b2s[o0+4], b2s[o0+5]);
        ull a3p = pack2(b2s[o0+6], b2s[o0+7]);
        #pragma unroll
        for (int f=0;f<32;f++){
            const ulonglong2* wr = (const ulonglong2*)&W2s[f*128 + o0];
            ulonglong2 wa = wr[0], wb = wr[1];
            a0p = fma2(wa.x, hbp[f], a0p);
            a1p = fma2(wa.y, hbp[f], a1p);
            a2p = fma2(wb.x, hbp[f], a2p);
            a3p = fma2(wb.y, hbp[f], a3p);
        }
        float y[8];
        unpack2(a0p, y[0], y[1]);
        unpack2(a1p, y[2], y[3]);
        unpack2(a2p, y[4], y[5]);
        unpack2(a3p, y[6], y[7]);
        #pragma unroll
        for (int j=0;j<8;j++){
            int o = o0 + j;
            float yv = geluf(y[j]);
            float ao = sA[o]*zb[(size_t)o*LL] + sB[o];
            pb[(size_t)o*LL] = w0*yv + w1*ao;
        }
    }
}

// ------------------- stats for g_pre -------------------
// grid (C, 64); block 256.
__global__ void K_statsP(){
    int c = blockIdx.x, j = blockIdx.y;
    int b = j >> 2, lq = j & 3;
    const float* p = g_pre + ((size_t)b*CC + c)*LL + lq*4096;
    int tid = threadIdx.x;
    float s = 0.f, s2 = 0.f;
    #pragma unroll
    for (int i=0;i<16;i++){ float v = p[i*256 + tid]; s += v; s2 += v*v; }
    s = warpRedSum(s); s2 = warpRedSum(s2);
    __shared__ float r1[8], r2[8];
    int w = tid >> 5, ln = tid & 31;
    if (ln == 0){ r1[w] = s; r2[w] = s2; }
    __syncthreads();
    if (tid == 0){
        float a = 0.f, bq = 0.f;
        #pragma unroll
        for (int i=0;i<8;i++){ a += r1[i]; bq += r2[i]; }
        atomicAdd(&g_stats[8*CC + c], (double)a);
        atomicAdd(&g_stats[9*CC + c], (double)bq);
    }
}

// ------------------- final BN affine -> d_out -------------------
__global__ void K_final(float* __restrict__ out){
    size_t i = ((size_t)blockIdx.x*256 + threadIdx.x)*4;
    int c = (int)((i >> 14) & 127);
    float4 v = *(const float4*)&g_pre[i];
    float A = g_A2[c], Bc = g_B2[c];
    float4 r;
    r.x = A*v.x + Bc; r.y = A*v.y + Bc; r.z = A*v.z + Bc; r.w = A*v.w + Bc;
    *(float4*)&out[i] = r;
}

// ------------------- launch -------------------
extern "C" void kernel_launch(void* const* d_in, const int* in_sizes, int n_in,
                              void* d_out, int out_size){
    const float* x         = (const float*)d_in[0];
    const float* dw_w      = (const float*)d_in[1];
    const float* bn2_g     = (const float*)d_in[2];
    const float* bn2_b     = (const float*)d_in[3];
    const float* pw_w      = (const float*)d_in[4];
    const float* pw_b      = (const float*)d_in[5];
    const float* add_w     = (const float*)d_in[6];
    const float* bn1_g     = (const float*)d_in[7];
    const float* bn1_b     = (const float*)d_in[8];
    const float* W1        = (const float*)d_in[9];
    const float* b1        = (const float*)d_in[10];
    const float* W2        = (const float*)d_in[11];
    const float* b2        = (const float*)d_in[12];
    const float* ffn_add_w = (const float*)d_in[13];
    const float* ffn_bn_g  = (const float*)d_in[14];
    const float* ffn_bn_b  = (const float*)d_in[15];
    float* out = (float*)d_out;

    K_zero<<<5,256>>>();
    K_dw<<<dim3(2,CC,BB),256>>>(x, dw_w);
    K_prep<<<1,128>>>(bn2_g, bn2_b, pw_w, pw_b);
    K_pwkv<<<dim3(LK/64,BB,2),128>>>();
    K_krow<<<BB*CC,256>>>();
    K_kv<<<BB*NH,256>>>();
    K_pwatt<<<dim3(LL/64,BB),128>>>(x, add_w);
    K_bnaff<<<1,128>>>(0, bn1_g, bn1_b);
    K_ffn<<<dim3(LL/256,BB),256>>>(W1, b1, W2, b2, ffn_add_w);
    K_statsP<<<dim3(CC,64),256>>>();
    K_bnaff<<<1,128>>>(1, ffn_bn_g, ffn_bn_b);
    K_final<<<(BB*CC*LL)/(256*4),256>>>(out);
}

// round 14
// speedup vs baseline: 1.6029x; 1.0557x over previous
#include <cuda_runtime.h>
#include <cuda_bf16.h>
#include <cstdint>
#include <math.h>

#define BB 16
#define CC 128
#define LL 16384
#define LK 4096
#define NH 8
#define DH 16

typedef unsigned long long ull;

// ------------------- scratch (device globals; no allocations) -------------------
__device__ float g_dwq[BB*CC*LL];
__device__ float g_dwk[BB*CC*LK];
__device__ float g_dwv[BB*CC*LK];
__device__ float g_k  [BB*CC*LK];
__device__ float g_v  [BB*CC*LK];
__device__ float g_z  [BB*CC*LL];
__device__ float g_pre[BB*CC*LL];
__device__ float g_kv [BB*NH*DH*DH];
__device__ float g_km [BB*CC];
__device__ float g_kis[BB*CC];
__device__ __align__(16) __nv_bfloat16 g_whi[3*CC*CC];
__device__ __align__(16) __nv_bfloat16 g_wlo[3*CC*CC];
__device__ float g_beff[3*CC];
__device__ float g_A1[CC], g_B1[CC], g_A2[CC], g_B2[CC];
// slots: 0/1 dwq, 2/3 dwk, 4/5 dwv, 6/7 z, 8/9 pre
__device__ double g_stats[10*CC];

// ------------------- helpers -------------------
__device__ __forceinline__ float geluf(float x){
    return 0.5f * x * (1.0f + erff(x * 0.70710678118654752440f));
}
__device__ __forceinline__ float warpRedSum(float v){
    v += __shfl_xor_sync(0xffffffffu, v, 16);
    v += __shfl_xor_sync(0xffffffffu, v, 8);
    v += __shfl_xor_sync(0xffffffffu, v, 4);
    v += __shfl_xor_sync(0xffffffffu, v, 2);
    v += __shfl_xor_sync(0xffffffffu, v, 1);
    return v;
}
__device__ __forceinline__ ull pack2(float lo, float hi){
    ull r; unsigned a = __float_as_uint(lo), b = __float_as_uint(hi);
    asm("mov.b64 %0, {%1,%2};" : "=l"(r) : "r"(a), "r"(b));
    return r;
}
__device__ __forceinline__ void unpack2(ull v, float& lo, float& hi){
    unsigned a, b;
    asm("mov.b64 {%0,%1}, %2;" : "=r"(a), "=r"(b) : "l"(v));
    lo = __uint_as_float(a); hi = __uint_as_float(b);
}
__device__ __forceinline__ ull fma2(ull a, ull b, ull c){
    ull d;
    asm("fma.rn.f32x2 %0, %1, %2, %3;" : "=l"(d) : "l"(a), "l"(b), "l"(c));
    return d;
}
__device__ __forceinline__ void blockAccum(float v, double* dst, float* red){
    v = warpRedSum(v);
    int w = threadIdx.x >> 5, ln = threadIdx.x & 31;
    if (ln == 0) red[w] = v;
    __syncthreads();
    if (threadIdx.x == 0){
        float s = 0.f;
        #pragma unroll
        for (int i=0;i<8;i++) s += red[i];
        atomicAdd(dst, (double)s);
    }
    __syncthreads();
}
__device__ __forceinline__ uint32_t s2u(const void* p){
    uint32_t a;
    asm("{ .reg .u64 t; cvta.to.shared.u64 t, %1; cvt.u32.u64 %0, t; }" : "=r"(a) : "l"(p));
    return a;
}

// ------------------- warp-MMA primitives (portable PTX, sm_80+) -------------------
#define LDM4(r0,r1,r2,r3, adr) \
    asm volatile("ldmatrix.sync.aligned.m8n8.x4.shared.b16 {%0,%1,%2,%3}, [%4];" \
        : "=r"(r0), "=r"(r1), "=r"(r2), "=r"(r3) : "r"(adr))

#define MMAB(d, a, b0, b1) \
    asm volatile("mma.sync.aligned.m16n8k16.row.col.f32.bf16.bf16.f32 " \
        "{%0,%1,%2,%3}, {%4,%5,%6,%7}, {%8,%9}, {%0,%1,%2,%3};" \
        : "+f"((d)[0]), "+f"((d)[1]), "+f"((d)[2]), "+f"((d)[3]) \
        : "r"((a)[0]), "r"((a)[1]), "r"((a)[2]), "r"((a)[3]), "r"(b0), "r"(b1))

// smem layout (bytes):
//  [0, 32768)       Wh: 128 rows x 256B (bf16 [o][k], chunk-XOR swizzle)
//  [32768, 65536)   Wl
//  [65536, 81920)   Xh: 64 rows x 256B (bf16 [l][k], same swizzle)   } pwatt: Qs overlays
//  [81920, 98304)   Xl                                               } [65536,100352)
//  pwatt: [100352, 108544) kvs
#define OFF_WL 32768
#define OFF_X  65536
#define OFF_XL 16384
#define PWKV_SMEM  98304
#define OFF_KV2 100352
#define PWATT_SMEM 108544

// ------------------- zero stats -------------------
__global__ void K_zero(){
    int i = blockIdx.x*256 + threadIdx.x;
    if (i < 10*CC) g_stats[i] = 0.0;
}

// ------------------- depthwise 3x3, 3 branches + fused BN stats -------------------
__global__ void K_dw(const float* __restrict__ x, const float* __restrict__ dw_w){
    __shared__ float im[66*128];
    __shared__ float red[8];
    int r0 = blockIdx.x*64, c = blockIdx.y, b = blockIdx.z;
    int tid = threadIdx.x;
    const float* xc = x + ((size_t)b*CC + c)*LL;
    #pragma unroll
    for (int i=0;i<33;i++){
        int e = i*256 + tid;
        int rr = e >> 7, w = e & 127;
        int gr = r0 - 1 + rr;
        im[e] = (gr >= 0 && gr < 128) ? xc[gr*128 + w] : 0.0f;
    }
    float wq[9], wk[9], wv[9];
    #pragma unroll
    for (int k=0;k<9;k++){
        wq[k] = dw_w[c*9 + k];
        wk[k] = dw_w[(CC   + c)*9 + k];
        wv[k] = dw_w[(2*CC + c)*9 + k];
    }
    __syncthreads();
    float sq=0.f, sq2=0.f, sk=0.f, sk2=0.f, sv=0.f, sv2=0.f;
    float* outq = g_dwq + ((size_t)b*CC + c)*LL + r0*128;
    #pragma unroll 2
    for (int i=0;i<32;i++){
        int s = i*256 + tid;
        int hl = s >> 7, w = s & 127;
        float acc = 0.f;
        #pragma unroll
        for (int ky=0;ky<3;ky++){
            const float* row = im + (hl+ky)*128 + w;
            if (w > 0)   acc += wq[ky*3+0] * row[-1];
                         acc += wq[ky*3+1] * row[0];
            if (w < 127) acc += wq[ky*3+2] * row[1];
        }
        outq[s] = acc;
        sq += acc; sq2 += acc*acc;
    }
    float* outk = g_dwk + ((size_t)b*CC + c)*LK + (r0>>1)*64;
    float* outv = g_dwv + ((size_t)b*CC + c)*LK + (r0>>1)*64;
    #pragma unroll
    for (int i=0;i<8;i++){
        int s = i*256 + tid;
        int ho = s >> 6, wo = s & 63;
        float ak = 0.f, av = 0.f;
        #pragma unroll
        for (int ky=0;ky<3;ky++){
            const float* row = im + (2*ho+ky)*128 + 2*wo;
            if (wo > 0){ ak += wk[ky*3+0]*row[-1]; av += wv[ky*3+0]*row[-1]; }
            ak += wk[ky*3+1]*row[0]; av += wv[ky*3+1]*row[0];
            ak += wk[ky*3+2]*row[1]; av += wv[ky*3+2]*row[1];
        }
        outk[s] = ak; outv[s] = av;
        sk += ak; sk2 += ak*ak; sv += av; sv2 += av*av;
    }
    __syncthreads();
    blockAccum(sq,  &g_stats[0*CC + c], red);
    blockAccum(sq2, &g_stats[1*CC + c], red);
    blockAccum(sk,  &g_stats[2*CC + c], red);
    blockAccum(sk2, &g_stats[3*CC + c], red);
    blockAccum(sv,  &g_stats[4*CC + c], red);
    blockAccum(sv2, &g_stats[5*CC + c], red);
}

// ------------------- fold BN2d into pointwise weights (+ bf16 hi/lo split) -------------------
__global__ void K_prep(const float* __restrict__ bn2_g, const float* __restrict__ bn2_b,
                       const float* __restrict__ pw_w, const float* __restrict__ pw_b){
    __shared__ float alpha[CC], beta[CC];
    int t = threadIdx.x;  // 128
    for (int i=0;i<3;i++){
        double cnt = (i==0) ? (double)BB*(double)LL : (double)BB*(double)LK;
        double m = g_stats[(size_t)(2*i)*CC + t] / cnt;
        double v = g_stats[(size_t)(2*i+1)*CC + t] / cnt - m*m;
        float A = bn2_g[i*CC + t] * rsqrtf((float)v + 1e-5f);
        alpha[t] = A;
        beta[t]  = bn2_b[i*CC + t] - (float)m * A;
        __syncthreads();
        float acc = pw_b[i*CC + t];
        const float* wrow = pw_w + (size_t)(i*CC + t)*CC;
        __nv_bfloat16* whrow = g_whi + (size_t)(i*CC + t)*CC;
        __nv_bfloat16* wlrow = g_wlo + (size_t)(i*CC + t)*CC;
        for (int c2=0;c2<CC;c2++){
            float w = wrow[c2];
            float we = w * alpha[c2];
            __nv_bfloat16 hi = __float2bfloat16_rn(we);
            whrow[c2] = hi;
            wlrow[c2] = __float2bfloat16_rn(we - __bfloat162float(hi));
            acc += w * beta[c2];
        }
        g_beff[i*CC + t] = acc;
        __syncthreads();
    }
}

// ------------------- staging -------------------
// W: bf16 [o][k], 256B rows, chunk (16B) index XOR'd with (o&7) for conflict-free LDSM.
__device__ __forceinline__ void stageW(char* sm, int which, int tid){
    const uint32_t* wh = (const uint32_t*)(g_whi + (size_t)which*CC*CC);
    const uint32_t* wl = (const uint32_t*)(g_wlo + (size_t)which*CC*CC);
    #pragma unroll
    for (int i=0;i<64;i++){
        int e = i*128 + tid;
        int o = e >> 6, kp = e & 63;
        uint32_t off = (uint32_t)(o*256 + ((((kp>>2) ^ (o&7)))<<4) + ((kp&3)<<2));
        *(uint32_t*)(sm + off)          = wh[o*64 + kp];
        *(uint32_t*)(sm + OFF_WL + off) = wl[o*64 + kp];
    }
}
// X: bf16 [l][k] (transposed), 64 rows x 256B, same swizzle keyed on (l&7).
__device__ __forceinline__ void stageX(char* sm, const float* sp, int Ls, int tid){
    #pragma unroll
    for (int i=0;i<32;i++){
        int e = i*128 + tid;
        int l = e & 63, kp = e >> 6;   // kp = k/2, 0..63
        float x0 = sp[(size_t)(2*kp)  *Ls + l];
        float x1 = sp[(size_t)(2*kp+1)*Ls + l];
        __nv_bfloat16 h0 = __float2bfloat16_rn(x0);
        __nv_bfloat16 h1 = __float2bfloat16_rn(x1);
        __nv_bfloat16 q0 = __float2bfloat16_rn(x0 - __bfloat162float(h0));
        __nv_bfloat16 q1 = __float2bfloat16_rn(x1 - __bfloat162float(h1));
        uint32_t hp = (uint32_t)__bfloat16_as_ushort(h0) | ((uint32_t)__bfloat16_as_ushort(h1)<<16);
        uint32_t lp = (uint32_t)__bfloat16_as_ushort(q0) | ((uint32_t)__bfloat16_as_ushort(q1)<<16);
        uint32_t off = (uint32_t)(l*256 + ((((kp>>2) ^ (l&7)))<<4) + ((kp&3)<<2));
        *(uint32_t*)(sm + OFF_X + off)          = hp;
        *(uint32_t*)(sm + OFF_X + OFF_XL + off) = lp;
    }
}

// ------------------- warp-MMA GEMM: 128o x 64l tile, 4 warps, 3-term bf16 split -------------------
__device__ __forceinline__ void gemmMMA(char* sm, int tid, float acc[2][8][4]){
    int lane = tid & 31, w = tid >> 5;
    int m = lane >> 3, li = lane & 7;
    uint32_t sb = s2u(sm);
    int arow0 = w*32 + (m&1)*8 + li;
    int brow0 = (m&1)*8 + li;
    int chalf = m >> 1;
    #pragma unroll
    for (int ks=0; ks<8; ks++){
        int c = 2*ks + chalf;
        uint32_t ah[2][4], al[2][4];
        #pragma unroll
        for (int mt=0; mt<2; mt++){
            int row = arow0 + mt*16;
            uint32_t adr = sb + (uint32_t)(row*256 + ((c ^ (row&7))<<4));
            LDM4(ah[mt][0],ah[mt][1],ah[mt][2],ah[mt][3], adr);
            LDM4(al[mt][0],al[mt][1],al[mt][2],al[mt][3], adr + OFF_WL);
        }
        #pragma unroll
        for (int nb=0; nb<4; nb++){
            int row = nb*16 + brow0;
            uint32_t adr = sb + OFF_X + (uint32_t)(row*256 + ((c ^ (row&7))<<4));
            uint32_t bh[4], bl[4];
            LDM4(bh[0],bh[1],bh[2],bh[3], adr);
            LDM4(bl[0],bl[1],bl[2],bl[3], adr + OFF_XL);
            #pragma unroll
            for (int mt=0; mt<2; mt++){
                MMAB(acc[mt][2*nb],   ah[mt], bh[0], bh[2]);
                MMAB(acc[mt][2*nb],   ah[mt], bl[0], bl[2]);
                MMAB(acc[mt][2*nb],   al[mt], bh[0], bh[2]);
                MMAB(acc[mt][2*nb+1], ah[mt], bh[1], bh[3]);
                MMAB(acc[mt][2*nb+1], ah[mt], bl[1], bl[3]);
                MMAB(acc[mt][2*nb+1], al[mt], bh[1], bh[3]);
            }
        }
    }
}

// ------------------- pointwise GEMM for k/v (tensor cores) -------------------
// grid (LK/256, B, 2); block 128.
__global__ void K_pwkvT(){
    extern __shared__ char sm[];
    int which = blockIdx.z + 1;
    const float* src  = (which==1) ? g_dwk : g_dwv;
    float*       dst  = (which==1) ? g_k   : g_v;
    const float* bias = g_beff + which*CC;
    int tid = threadIdx.x, lane = tid & 31, w = tid >> 5;
    int b = blockIdx.y, base_l = blockIdx.x*256;
    stageW(sm, which, tid);
    const float* srcb = src + (size_t)b*CC*LK;
    float*       dstb = dst + (size_t)b*CC*LK;
    int o0 = w*32 + (lane>>2), lc = 2*(lane&3);
    for (int it=0; it<4; it++){
        int l0 = base_l + it*64;
        __syncthreads();
        stageX(sm, srcb + l0, LK, tid);
        __syncthreads();
        float acc[2][8][4];
        #pragma unroll
        for (int mt=0;mt<2;mt++)
            #pragma unroll
            for (int nt=0;nt<8;nt++)
                #pragma unroll
                for (int r=0;r<4;r++) acc[mt][nt][r] = 0.f;
        gemmMMA(sm, tid, acc);
        #pragma unroll
        for (int mt=0;mt<2;mt++){
            int o = o0 + mt*16;
            float bva = bias[o], bvb = bias[o+8];
            #pragma unroll
            for (int nt=0;nt<8;nt++){
                int l = l0 + nt*8 + lc;
                float2 r0, r1;
                r0.x = geluf(acc[mt][nt][0] + bva);
                r0.y = geluf(acc[mt][nt][1] + bva);
                r1.x = geluf(acc[mt][nt][2] + bvb);
                r1.y = geluf(acc[mt][nt][3] + bvb);
                *(float2*)&dstb[(size_t)o*LK + l]     = r0;
                *(float2*)&dstb[(size_t)(o+8)*LK + l] = r1;
            }
        }
    }
}

// ------------------- q GEMM (tensor cores) + GELU + attention + residual + z-stats -------------------
// grid (LL/256, B); block 128. Qs (stride 68) overlays the X region after mma completes.
__global__ void K_pwattT(const float* __restrict__ x, const float* __restrict__ add_w){
    extern __shared__ char sm[];
    float* Qs  = (float*)(sm + OFF_X);
    float* kvs = (float*)(sm + OFF_KV2);
    int tid = threadIdx.x, lane = tid & 31, w = tid >> 5;
    int b = blockIdx.y, base_l = blockIdx.x*256;
    {
        const float* kvp = g_kv + (size_t)b*NH*DH*DH;
        for (int i=tid;i<NH*DH*DH;i+=128) kvs[i] = kvp[i];
    }
    stageW(sm, 0, tid);
    float a0 = fmaxf(add_w[0], 0.f), a1 = fmaxf(add_w[1], 0.f);
    float inv = 1.f / (a0 + a1 + 1e-12f);
    float w0 = a0*inv, w1 = a1*inv;
    const float* srcb = g_dwq + (size_t)b*CC*LL;
    const float* xb0  = x     + (size_t)b*CC*LL;
    float*       zb0  = g_z   + (size_t)b*CC*LL;
    int o0 = w*32 + (lane>>2), lc = 2*(lane&3);
    float zs = 0.f, zs2 = 0.f;
    for (int it=0; it<4; it++){
        int l0 = base_l + it*64;
        __syncthreads();
        stageX(sm, srcb + l0, LL, tid);
        __syncthreads();
        float acc[2][8][4];
        #pragma unroll
        for (int mt=0;mt<2;mt++)
            #pragma unroll
            for (int nt=0;nt<8;nt++)
                #pragma unroll
                for (int r=0;r<4;r++) acc[mt][nt][r] = 0.f;
        gemmMMA(sm, tid, acc);
        __syncthreads();   // all warps done reading X; Qs may overwrite it
        #pragma unroll
        for (int mt=0;mt<2;mt++){
            int o = o0 + mt*16;
            float bva = g_beff[o], bvb = g_beff[o+8];
            #pragma unroll
            for (int nt=0;nt<8;nt++){
                int l = nt*8 + lc;
                Qs[o*68 + l]       = geluf(acc[mt][nt][0] + bva);
                Qs[o*68 + l + 1]   = geluf(acc[mt][nt][1] + bva);
                Qs[(o+8)*68 + l]   = geluf(acc[mt][nt][2] + bvb);
                Qs[(o+8)*68 + l+1] = geluf(acc[mt][nt][3] + bvb);
            }
        }
        __syncthreads();
        // attention: thread handles token l (64 tokens) for 4 heads
        {
            int l = tid & 63, hb = (tid >> 6) * 4;
            #pragma unroll
            for (int hh=0;hh<4;hh++){
                int h = hb + hh;
                float qv[16], mx = -1e30f;
                #pragma unroll
                for (int d=0;d<16;d++){ qv[d] = Qs[(h*16+d)*68 + l]; mx = fmaxf(mx, qv[d]); }
                float s = 0.f;
                #pragma unroll
                for (int d=0;d<16;d++){ qv[d] = __expf(qv[d] - mx); s += qv[d]; }
                float is = 1.f / s;
                const float* kvh = kvs + h*256;
                float av[16];
                #pragma unroll
                for (int e=0;e<16;e++) av[e] = 0.f;
                #pragma unroll
                for (int d=0;d<16;d++){
                    float q = qv[d];
                    #pragma unroll
                    for (int e=0;e<16;e++) av[e] += q * kvh[d*16 + e];
                }
                #pragma unroll
                for (int e=0;e<16;e++) Qs[(h*16+e)*68 + l] = av[e] * is;
            }
        }
        __syncthreads();
        // residual addw + writeout + keep z in Qs for stats
        const float* xb = xb0 + l0;
        float*       zb = zb0 + l0;
        #pragma unroll 4
        for (int i=0;i<64;i++){
            int e = i*128 + tid;
            int c = e >> 6, lcc = e & 63;
            float att = Qs[c*68 + lcc];
            float zv = w0*att + w1*xb[(size_t)c*LL + lcc];
            zb[(size_t)c*LL + lcc] = zv;
            Qs[c*68 + lcc] = zv;
        }
        __syncthreads();
        // per-channel partial stats (thread tid owns channel tid)
        #pragma unroll 8
        for (int j=0;j<64;j++){ float v = Qs[tid*68 + j]; zs += v; zs2 += v*v; }
    }
    atomicAdd(&g_stats[6*CC + tid], (double)zs);
    atomicAdd(&g_stats[7*CC + tid], (double)zs2);
}

// ------------------- per-row max + sum(exp) of k -------------------
__global__ void K_krow(){
    int row = blockIdx.x;
    const float* p = g_k + (size_t)row*LK;
    int tid = threadIdx.x, w = tid >> 5, ln = tid & 31;
    float vals[16], m = -1e30f;
    #pragma unroll
    for (int i=0;i<16;i++){ vals[i] = p[i*256 + tid]; m = fmaxf(m, vals[i]); }
    #pragma unroll
    for (int o=16;o>0;o>>=1) m = fmaxf(m, __shfl_xor_sync(0xffffffffu, m, o));
    __shared__ float rm[8], rs[8];
    if (ln == 0) rm[w] = m;
    __syncthreads();
    float bm = rm[0];
    #pragma unroll
    for (int i=1;i<8;i++) bm = fmaxf(bm, rm[i]);
    float s = 0.f;
    #pragma unroll
    for (int i=0;i<16;i++) s += __expf(vals[i] - bm);
    s = warpRedSum(s);
    if (ln == 0) rs[w] = s;
    __syncthreads();
    if (tid == 0){
        float tot = 0.f;
        #pragma unroll
        for (int i=0;i<8;i++) tot += rs[i];
        g_km[row]  = bm;
        g_kis[row] = 1.f / tot;
    }
}

// ------------------- kv = softmax_n(k)^T @ v per (b,h) -------------------
__global__ void K_kv(){
    __shared__ float ks[16*257], vs[16*257];
    __shared__ float mrow[16], isrow[16];
    int bh = blockIdx.x; int b = bh >> 3, h = bh & 7;
    int tid = threadIdx.x; int d = tid >> 4, e = tid & 15;
    const float* kb = g_k + ((size_t)b*CC + h*16)*LK;
    const float* vb = g_v + ((size_t)b*CC + h*16)*LK;
    if (tid < 16){
        mrow[tid]  = g_km [b*CC + h*16 + tid];
        isrow[tid] = g_kis[b*CC + h*16 + tid];
    }
    __syncthreads();
    float acc = 0.f;
    for (int n0=0;n0<LK;n0+=256){
        __syncthreads();
        #pragma unroll
        for (int i=0;i<16;i++){
            ks[i*257 + tid] = __expf(kb[(size_t)i*LK + n0 + tid] - mrow[i]) * isrow[i];
            vs[i*257 + tid] = vb[(size_t)i*LK + n0 + tid];
        }
        __syncthreads();
        #pragma unroll 8
        for (int j=0;j<256;j++)
            acc += ks[d*257 + j] * vs[e*257 + j];
    }
    g_kv[((size_t)bh*16 + d)*16 + e] = acc;
}

// ------------------- BN1d affine coefficients -------------------
__global__ void K_bnaff(int sel, const float* __restrict__ g, const float* __restrict__ bt){
    int t = threadIdx.x;
    int slot = sel ? 8 : 6;
    double cnt = (double)BB * (double)LL;
    double m = g_stats[(size_t)slot*CC + t] / cnt;
    double v = g_stats[(size_t)(slot+1)*CC + t] / cnt - m*m;
    float a = g[t] * rsqrtf((float)v + 1e-5f);
    float bc = bt[t] - (float)m * a;
    if (sel){ g_A2[t] = a; g_B2[t] = bc; }
    else    { g_A1[t] = a; g_B1[t] = bc; }
}

// ------------------- FFN (128->32->128) f32x2 + residual addw -> g_pre -------------------
__global__ void K_ffn(const float* __restrict__ W1, const float* __restrict__ b1,
                      const float* __restrict__ W2, const float* __restrict__ b2,
                      const float* __restrict__ fw){
    __shared__ __align__(16) float W1s[128*32];
    __shared__ __align__(16) float W2s[32*128];
    __shared__ float b1s[32], b2s[128], sA[128], sB[128];
    int tid = threadIdx.x;
    int b = blockIdx.y;
    int l = blockIdx.x*256 + tid;
    #pragma unroll
    for (int i=0;i<16;i++){ W1s[i*256 + tid] = W1[i*256 + tid]; W2s[i*256 + tid] = W2[i*256 + tid]; }
    if (tid < 32) b1s[tid] = b1[tid];
    if (tid < 128){ b2s[tid] = b2[tid]; sA[tid] = g_A1[tid]; sB[tid] = g_B1[tid]; }
    __syncthreads();
    float a0 = fmaxf(fw[0], 0.f), a1 = fmaxf(fw[1], 0.f);
    float inv = 1.f / (a0 + a1 + 1e-12f);
    float w0 = a0*inv, w1 = a1*inv;
    const float* zb = g_z   + ((size_t)b*CC)*LL + l;
    float*       pb = g_pre + ((size_t)b*CC)*LL + l;
    ull hp[16];
    #pragma unroll
    for (int j=0;j<16;j++) hp[j] = pack2(b1s[2*j], b1s[2*j+1]);
    for (int c=0;c<128;c++){
        float xv = sA[c]*zb[(size_t)c*LL] + sB[c];
        ull xp = pack2(xv, xv);
        const ull* wr = (const ull*)&W1s[c*32];
        #pragma unroll
        for (int j=0;j<16;j++) hp[j] = fma2(wr[j], xp, hp[j]);
    }
    ull hbp[32];
    #pragma unroll
    for (int j=0;j<16;j++){
        float ha, hb2;
        unpack2(hp[j], ha, hb2);
        ha = geluf(ha); hb2 = geluf(hb2);
        hbp[2*j]   = pack2(ha, ha);
        hbp[2*j+1] = pack2(hb2, hb2);
    }
    for (int og=0;og<16;og++){
        int o0 = og*8;
        ull a0p = pack2(b2s[o0],   b2s[o0+1]);
        ull a1p = pack2(b2s[o0+2], b2s[o0+3]);
        ull a2p = pack2(b2s[o0+4], b2s[o0+5]);
        ull a3p = pack2(b2s[o0+6], b2s[o0+7]);
        #pragma unroll
        for (int f=0;f<32;f++){
            const ulonglong2* wr = (const ulonglong2*)&W2s[f*128 + o0];
            ulonglong2 wa = wr[0], wb = wr[1];
            a0p = fma2(wa.x, hbp[f], a0p);
            a1p = fma2(wa.y, hbp[f], a1p);
            a2p = fma2(wb.x, hbp[f], a2p);
            a3p = fma2(wb.y, hbp[f], a3p);
        }
        float y[8];
        unpack2(a0p, y[0], y[1]);
        unpack2(a1p, y[2], y[3]);
        unpack2(a2p, y[4], y[5]);
        unpack2(a3p, y[6], y[7]);
        #pragma unroll
        for (int j=0;j<8;j++){
            int o = o0 + j;
            float yv = geluf(y[j]);
            float ao = sA[o]*zb[(size_t)o*LL] + sB[o];
            pb[(size_t)o*LL] = w0*yv + w1*ao;
        }
    }
}

// ------------------- stats for g_pre -------------------
__global__ void K_statsP(){
    int c = blockIdx.x, j = blockIdx.y;
    int b = j >> 2, lq = j & 3;
    const float* p = g_pre + ((size_t)b*CC + c)*LL + lq*4096;
    int tid = threadIdx.x;
    float s = 0.f, s2 = 0.f;
    #pragma unroll
    for (int i=0;i<16;i++){ float v = p[i*256 + tid]; s += v; s2 += v*v; }
    s = warpRedSum(s); s2 = warpRedSum(s2);
    __shared__ float r1[8], r2[8];
    int w = tid >> 5, ln = tid & 31;
    if (ln == 0){ r1[w] = s; r2[w] = s2; }
    __syncthreads();
    if (tid == 0){
        float a = 0.f, bq = 0.f;
        #pragma unroll
        for (int i=0;i<8;i++){ a += r1[i]; bq += r2[i]; }
        atomicAdd(&g_stats[8*CC + c], (double)a);
        atomicAdd(&g_stats[9*CC + c], (double)bq);
    }
}

// ------------------- final BN affine -> d_out -------------------
__global__ void K_final(float* __restrict__ out){
    size_t i = ((size_t)blockIdx.x*256 + threadIdx.x)*4;
    int c = (int)((i >> 14) & 127);
    float4 v = *(const float4*)&g_pre[i];
    float A = g_A2[c], Bc = g_B2[c];
    float4 r;
    r.x = A*v.x + Bc; r.y = A*v.y + Bc; r.z = A*v.z + Bc; r.w = A*v.w + Bc;
    *(float4*)&out[i] = r;
}

// ------------------- launch -------------------
extern "C" void kernel_launch(void* const* d_in, const int* in_sizes, int n_in,
                              void* d_out, int out_size){
    const float* x         = (const float*)d_in[0];
    const float* dw_w      = (const float*)d_in[1];
    const float* bn2_g     = (const float*)d_in[2];
    const float* bn2_b     = (const float*)d_in[3];
    const float* pw_w      = (const float*)d_in[4];
    const float* pw_b      = (const float*)d_in[5];
    const float* add_w     = (const float*)d_in[6];
    const float* bn1_g     = (const float*)d_in[7];
    const float* bn1_b     = (const float*)d_in[8];
    const float* W1        = (const float*)d_in[9];
    const float* b1        = (const float*)d_in[10];
    const float* W2        = (const float*)d_in[11];
    const float* b2        = (const float*)d_in[12];
    const float* ffn_add_w = (const float*)d_in[13];
    const float* ffn_bn_g  = (const float*)d_in[14];
    const float* ffn_bn_b  = (const float*)d_in[15];
    float* out = (float*)d_out;

    cudaFuncSetAttribute(K_pwkvT,  cudaFuncAttributeMaxDynamicSharedMemorySize, PWKV_SMEM);
    cudaFuncSetAttribute(K_pwattT, cudaFuncAttributeMaxDynamicSharedMemorySize, PWATT_SMEM);

    K_zero<<<5,256>>>();
    K_dw<<<dim3(2,CC,BB),256>>>(x, dw_w);
    K_prep<<<1,128>>>(bn2_g, bn2_b, pw_w, pw_b);
    K_pwkvT<<<dim3(LK/256,BB,2),128,PWKV_SMEM>>>();
    K_krow<<<BB*CC,256>>>();
    K_kv<<<BB*NH,256>>>();
    K_pwattT<<<dim3(LL/256,BB),128,PWATT_SMEM>>>(x, add_w);
    K_bnaff<<<1,128>>>(0, bn1_g, bn1_b);
    K_ffn<<<dim3(LL/256,BB),256>>>(W1, b1, W2, b2, ffn_add_w);
    K_statsP<<<dim3(CC,64),256>>>();
    K_bnaff<<<1,128>>>(1, ffn_bn_g, ffn_bn_b);
    K_final<<<(BB*CC*LL)/(256*4),256>>>(out);
}

// round 15
// speedup vs baseline: 1.6425x; 1.0247x over previous
#include <cuda_runtime.h>
#include <cuda_bf16.h>
#include <cstdint>
#include <math.h>

#define BB 16
#define CC 128
#define LL 16384
#define LK 4096
#define NH 8
#define DH 16

typedef unsigned long long ull;

// ------------------- scratch (device globals; no allocations) -------------------
__device__ float g_dwq[BB*CC*LL];
__device__ float g_dwk[BB*CC*LK];
__device__ float g_dwv[BB*CC*LK];
__device__ float g_k  [BB*CC*LK];
__device__ float g_v  [BB*CC*LK];
__device__ float g_z  [BB*CC*LL];
__device__ float g_pre[BB*CC*LL];
__device__ float g_kv [BB*NH*DH*DH];
__device__ float g_km [BB*CC];
__device__ float g_kis[BB*CC];
__device__ __align__(16) __nv_bfloat16 g_whi[3*CC*CC];
__device__ __align__(16) __nv_bfloat16 g_wlo[3*CC*CC];
__device__ __align__(16) __nv_bfloat16 g_w1h[32*CC];
__device__ __align__(16) __nv_bfloat16 g_w1l[32*CC];
__device__ __align__(16) __nv_bfloat16 g_w2h[CC*32];
__device__ __align__(16) __nv_bfloat16 g_w2l[CC*32];
__device__ float g_beff[3*CC];
__device__ float g_A1[CC], g_B1[CC], g_A2[CC], g_B2[CC];
// slots: 0/1 dwq, 2/3 dwk, 4/5 dwv, 6/7 z, 8/9 pre
__device__ double g_stats[10*CC];

// ------------------- helpers -------------------
__device__ __forceinline__ float geluf(float x){
    return 0.5f * x * (1.0f + erff(x * 0.70710678118654752440f));
}
__device__ __forceinline__ float warpRedSum(float v){
    v += __shfl_xor_sync(0xffffffffu, v, 16);
    v += __shfl_xor_sync(0xffffffffu, v, 8);
    v += __shfl_xor_sync(0xffffffffu, v, 4);
    v += __shfl_xor_sync(0xffffffffu, v, 2);
    v += __shfl_xor_sync(0xffffffffu, v, 1);
    return v;
}
__device__ __forceinline__ void blockAccum(float v, double* dst, float* red){
    v = warpRedSum(v);
    int w = threadIdx.x >> 5, ln = threadIdx.x & 31;
    if (ln == 0) red[w] = v;
    __syncthreads();
    if (threadIdx.x == 0){
        float s = 0.f;
        #pragma unroll
        for (int i=0;i<8;i++) s += red[i];
        atomicAdd(dst, (double)s);
    }
    __syncthreads();
}
__device__ __forceinline__ uint32_t s2u(const void* p){
    uint32_t a;
    asm("{ .reg .u64 t; cvta.to.shared.u64 t, %1; cvt.u32.u64 %0, t; }" : "=r"(a) : "l"(p));
    return a;
}

// ------------------- warp-MMA primitives (portable PTX, sm_80+) -------------------
#define LDM4(r0,r1,r2,r3, adr) \
    asm volatile("ldmatrix.sync.aligned.m8n8.x4.shared.b16 {%0,%1,%2,%3}, [%4];" \
        : "=r"(r0), "=r"(r1), "=r"(r2), "=r"(r3) : "r"(adr))

#define MMAB(d, a, b0, b1) \
    asm volatile("mma.sync.aligned.m16n8k16.row.col.f32.bf16.bf16.f32 " \
        "{%0,%1,%2,%3}, {%4,%5,%6,%7}, {%8,%9}, {%0,%1,%2,%3};" \
        : "+f"((d)[0]), "+f"((d)[1]), "+f"((d)[2]), "+f"((d)[3]) \
        : "r"((a)[0]), "r"((a)[1]), "r"((a)[2]), "r"((a)[3]), "r"(b0), "r"(b1))

// pw smem layout (bytes)
#define OFF_WL 32768
#define OFF_X  65536
#define OFF_XL 16384
#define PWKV_SMEM  98304
#define OFF_KV2 100352
#define PWATT_SMEM 108544

// FFN smem layout (bytes)
#define FO_W1  0
#define FO_W1L 8192
#define FO_Z   16384
#define FO_ZL  32768
#define FO_W2  49152
#define FO_W2L 65536
#define FO_H   81920
#define FO_HL  90112
#define FO_MISC 98304
#define FFN_SMEM 100352

// ------------------- zero stats -------------------
__global__ void K_zero(){
    int i = blockIdx.x*256 + threadIdx.x;
    if (i < 10*CC) g_stats[i] = 0.0;
}

// ------------------- depthwise 3x3, 3 branches + fused BN stats -------------------
__global__ void K_dw(const float* __restrict__ x, const float* __restrict__ dw_w){
    __shared__ float im[66*128];
    __shared__ float red[8];
    int r0 = blockIdx.x*64, c = blockIdx.y, b = blockIdx.z;
    int tid = threadIdx.x;
    const float* xc = x + ((size_t)b*CC + c)*LL;
    #pragma unroll
    for (int i=0;i<33;i++){
        int e = i*256 + tid;
        int rr = e >> 7, w = e & 127;
        int gr = r0 - 1 + rr;
        im[e] = (gr >= 0 && gr < 128) ? xc[gr*128 + w] : 0.0f;
    }
    float wq[9], wk[9], wv[9];
    #pragma unroll
    for (int k=0;k<9;k++){
        wq[k] = dw_w[c*9 + k];
        wk[k] = dw_w[(CC   + c)*9 + k];
        wv[k] = dw_w[(2*CC + c)*9 + k];
    }
    __syncthreads();
    float sq=0.f, sq2=0.f, sk=0.f, sk2=0.f, sv=0.f, sv2=0.f;
    float* outq = g_dwq + ((size_t)b*CC + c)*LL + r0*128;
    #pragma unroll 2
    for (int i=0;i<32;i++){
        int s = i*256 + tid;
        int hl = s >> 7, w = s & 127;
        float acc = 0.f;
        #pragma unroll
        for (int ky=0;ky<3;ky++){
            const float* row = im + (hl+ky)*128 + w;
            if (w > 0)   acc += wq[ky*3+0] * row[-1];
                         acc += wq[ky*3+1] * row[0];
            if (w < 127) acc += wq[ky*3+2] * row[1];
        }
        outq[s] = acc;
        sq += acc; sq2 += acc*acc;
    }
    float* outk = g_dwk + ((size_t)b*CC + c)*LK + (r0>>1)*64;
    float* outv = g_dwv + ((size_t)b*CC + c)*LK + (r0>>1)*64;
    #pragma unroll
    for (int i=0;i<8;i++){
        int s = i*256 + tid;
        int ho = s >> 6, wo = s & 63;
        float ak = 0.f, av = 0.f;
        #pragma unroll
        for (int ky=0;ky<3;ky++){
            const float* row = im + (2*ho+ky)*128 + 2*wo;
            if (wo > 0){ ak += wk[ky*3+0]*row[-1]; av += wv[ky*3+0]*row[-1]; }
            ak += wk[ky*3+1]*row[0]; av += wv[ky*3+1]*row[0];
            ak += wk[ky*3+2]*row[1]; av += wv[ky*3+2]*row[1];
        }
        outk[s] = ak; outv[s] = av;
        sk += ak; sk2 += ak*ak; sv += av; sv2 += av*av;
    }
    __syncthreads();
    blockAccum(sq,  &g_stats[0*CC + c], red);
    blockAccum(sq2, &g_stats[1*CC + c], red);
    blockAccum(sk,  &g_stats[2*CC + c], red);
    blockAccum(sk2, &g_stats[3*CC + c], red);
    blockAccum(sv,  &g_stats[4*CC + c], red);
    blockAccum(sv2, &g_stats[5*CC + c], red);
}

// ------------------- fold BN2d into pointwise weights + all bf16 splits -------------------
__global__ void K_prep(const float* __restrict__ bn2_g, const float* __restrict__ bn2_b,
                       const float* __restrict__ pw_w, const float* __restrict__ pw_b,
                       const float* __restrict__ W1, const float* __restrict__ W2){
    __shared__ float alpha[CC], beta[CC];
    int t = threadIdx.x;  // 128
    for (int i=0;i<3;i++){
        double cnt = (i==0) ? (double)BB*(double)LL : (double)BB*(double)LK;
        double m = g_stats[(size_t)(2*i)*CC + t] / cnt;
        double v = g_stats[(size_t)(2*i+1)*CC + t] / cnt - m*m;
        float A = bn2_g[i*CC + t] * rsqrtf((float)v + 1e-5f);
        alpha[t] = A;
        beta[t]  = bn2_b[i*CC + t] - (float)m * A;
        __syncthreads();
        float acc = pw_b[i*CC + t];
        const float* wrow = pw_w + (size_t)(i*CC + t)*CC;
        __nv_bfloat16* whrow = g_whi + (size_t)(i*CC + t)*CC;
        __nv_bfloat16* wlrow = g_wlo + (size_t)(i*CC + t)*CC;
        for (int c2=0;c2<CC;c2++){
            float w = wrow[c2];
            float we = w * alpha[c2];
            __nv_bfloat16 hi = __float2bfloat16_rn(we);
            whrow[c2] = hi;
            wlrow[c2] = __float2bfloat16_rn(we - __bfloat162float(hi));
            acc += w * beta[c2];
        }
        g_beff[i*CC + t] = acc;
        __syncthreads();
    }
    // W1^T split: g_w1h[f][c] = W1[c][f]
    for (int f=0; f<32; f++){
        float w = W1[t*32 + f];
        __nv_bfloat16 hi = __float2bfloat16_rn(w);
        g_w1h[f*CC + t] = hi;
        g_w1l[f*CC + t] = __float2bfloat16_rn(w - __bfloat162float(hi));
    }
    // W2^T split: g_w2h[o][f] = W2[f][o]
    for (int f=0; f<32; f++){
        float w = W2[f*CC + t];
        __nv_bfloat16 hi = __float2bfloat16_rn(w);
        g_w2h[t*32 + f] = hi;
        g_w2l[t*32 + f] = __float2bfloat16_rn(w - __bfloat162float(hi));
    }
}

// ------------------- staging for pointwise GEMMs -------------------
__device__ __forceinline__ void stageW(char* sm, int which, int tid){
    const uint32_t* wh = (const uint32_t*)(g_whi + (size_t)which*CC*CC);
    const uint32_t* wl = (const uint32_t*)(g_wlo + (size_t)which*CC*CC);
    #pragma unroll
    for (int i=0;i<64;i++){
        int e = i*128 + tid;
        int o = e >> 6, kp = e & 63;
        uint32_t off = (uint32_t)(o*256 + ((((kp>>2) ^ (o&7)))<<4) + ((kp&3)<<2));
        *(uint32_t*)(sm + off)          = wh[o*64 + kp];
        *(uint32_t*)(sm + OFF_WL + off) = wl[o*64 + kp];
    }
}
__device__ __forceinline__ void stageX(char* sm, const float* sp, int Ls, int tid){
    #pragma unroll
    for (int i=0;i<32;i++){
        int e = i*128 + tid;
        int l = e & 63, kp = e >> 6;
        float x0 = sp[(size_t)(2*kp)  *Ls + l];
        float x1 = sp[(size_t)(2*kp+1)*Ls + l];
        __nv_bfloat16 h0 = __float2bfloat16_rn(x0);
        __nv_bfloat16 h1 = __float2bfloat16_rn(x1);
        __nv_bfloat16 q0 = __float2bfloat16_rn(x0 - __bfloat162float(h0));
        __nv_bfloat16 q1 = __float2bfloat16_rn(x1 - __bfloat162float(h1));
        uint32_t hp = (uint32_t)__bfloat16_as_ushort(h0) | ((uint32_t)__bfloat16_as_ushort(h1)<<16);
        uint32_t lp = (uint32_t)__bfloat16_as_ushort(q0) | ((uint32_t)__bfloat16_as_ushort(q1)<<16);
        uint32_t off = (uint32_t)(l*256 + ((((kp>>2) ^ (l&7)))<<4) + ((kp&3)<<2));
        *(uint32_t*)(sm + OFF_X + off)          = hp;
        *(uint32_t*)(sm + OFF_X + OFF_XL + off) = lp;
    }
}

// ------------------- warp-MMA GEMM: 128o x 64l tile, 4 warps, 3-term bf16 split -------------------
__device__ __forceinline__ void gemmMMA(char* sm, int tid, float acc[2][8][4]){
    int lane = tid & 31, w = tid >> 5;
    int m = lane >> 3, li = lane & 7;
    uint32_t sb = s2u(sm);
    int arow0 = w*32 + (m&1)*8 + li;
    int brow0 = (m&1)*8 + li;
    int chalf = m >> 1;
    #pragma unroll
    for (int ks=0; ks<8; ks++){
        int c = 2*ks + chalf;
        uint32_t ah[2][4], al[2][4];
        #pragma unroll
        for (int mt=0; mt<2; mt++){
            int row = arow0 + mt*16;
            uint32_t adr = sb + (uint32_t)(row*256 + ((c ^ (row&7))<<4));
            LDM4(ah[mt][0],ah[mt][1],ah[mt][2],ah[mt][3], adr);
            LDM4(al[mt][0],al[mt][1],al[mt][2],al[mt][3], adr + OFF_WL);
        }
        #pragma unroll
        for (int nb=0; nb<4; nb++){
            int row = nb*16 + brow0;
            uint32_t adr = sb + OFF_X + (uint32_t)(row*256 + ((c ^ (row&7))<<4));
            uint32_t bh[4], bl[4];
            LDM4(bh[0],bh[1],bh[2],bh[3], adr);
            LDM4(bl[0],bl[1],bl[2],bl[3], adr + OFF_XL);
            #pragma unroll
            for (int mt=0; mt<2; mt++){
                MMAB(acc[mt][2*nb],   ah[mt], bh[0], bh[2]);
                MMAB(acc[mt][2*nb],   ah[mt], bl[0], bl[2]);
                MMAB(acc[mt][2*nb],   al[mt], bh[0], bh[2]);
                MMAB(acc[mt][2*nb+1], ah[mt], bh[1], bh[3]);
                MMAB(acc[mt][2*nb+1], ah[mt], bl[1], bl[3]);
                MMAB(acc[mt][2*nb+1], al[mt], bh[1], bh[3]);
            }
        }
    }
}

// ------------------- pointwise GEMM for k/v (tensor cores) -------------------
__global__ void K_pwkvT(){
    extern __shared__ char sm[];
    int which = blockIdx.z + 1;
    const float* src  = (which==1) ? g_dwk : g_dwv;
    float*       dst  = (which==1) ? g_k   : g_v;
    const float* bias = g_beff + which*CC;
    int tid = threadIdx.x, lane = tid & 31, w = tid >> 5;
    int b = blockIdx.y, base_l = blockIdx.x*256;
    stageW(sm, which, tid);
    const float* srcb = src + (size_t)b*CC*LK;
    float*       dstb = dst + (size_t)b*CC*LK;
    int o0 = w*32 + (lane>>2), lc = 2*(lane&3);
    for (int it=0; it<4; it++){
        int l0 = base_l + it*64;
        __syncthreads();
        stageX(sm, srcb + l0, LK, tid);
        __syncthreads();
        float acc[2][8][4];
        #pragma unroll
        for (int mt=0;mt<2;mt++)
            #pragma unroll
            for (int nt=0;nt<8;nt++)
                #pragma unroll
                for (int r=0;r<4;r++) acc[mt][nt][r] = 0.f;
        gemmMMA(sm, tid, acc);
        #pragma unroll
        for (int mt=0;mt<2;mt++){
            int o = o0 + mt*16;
            float bva = bias[o], bvb = bias[o+8];
            #pragma unroll
            for (int nt=0;nt<8;nt++){
                int l = l0 + nt*8 + lc;
                float2 r0, r1;
                r0.x = geluf(acc[mt][nt][0] + bva);
                r0.y = geluf(acc[mt][nt][1] + bva);
                r1.x = geluf(acc[mt][nt][2] + bvb);
                r1.y = geluf(acc[mt][nt][3] + bvb);
                *(float2*)&dstb[(size_t)o*LK + l]     = r0;
                *(float2*)&dstb[(size_t)(o+8)*LK + l] = r1;
            }
        }
    }
}

// ------------------- q GEMM (tensor cores) + GELU + attention + residual + z-stats -------------------
__global__ void K_pwattT(const float* __restrict__ x, const float* __restrict__ add_w){
    extern __shared__ char sm[];
    float* Qs  = (float*)(sm + OFF_X);
    float* kvs = (float*)(sm + OFF_KV2);
    int tid = threadIdx.x, lane = tid & 31, w = tid >> 5;
    int b = blockIdx.y, base_l = blockIdx.x*256;
    {
        const float* kvp = g_kv + (size_t)b*NH*DH*DH;
        for (int i=tid;i<NH*DH*DH;i+=128) kvs[i] = kvp[i];
    }
    stageW(sm, 0, tid);
    float a0 = fmaxf(add_w[0], 0.f), a1 = fmaxf(add_w[1], 0.f);
    float inv = 1.f / (a0 + a1 + 1e-12f);
    float w0 = a0*inv, w1 = a1*inv;
    const float* srcb = g_dwq + (size_t)b*CC*LL;
    const float* xb0  = x     + (size_t)b*CC*LL;
    float*       zb0  = g_z   + (size_t)b*CC*LL;
    int o0 = w*32 + (lane>>2), lc = 2*(lane&3);
    float zs = 0.f, zs2 = 0.f;
    for (int it=0; it<4; it++){
        int l0 = base_l + it*64;
        __syncthreads();
        stageX(sm, srcb + l0, LL, tid);
        __syncthreads();
        float acc[2][8][4];
        #pragma unroll
        for (int mt=0;mt<2;mt++)
            #pragma unroll
            for (int nt=0;nt<8;nt++)
                #pragma unroll
                for (int r=0;r<4;r++) acc[mt][nt][r] = 0.f;
        gemmMMA(sm, tid, acc);
        __syncthreads();
        #pragma unroll
        for (int mt=0;mt<2;mt++){
            int o = o0 + mt*16;
            float bva = g_beff[o], bvb = g_beff[o+8];
            #pragma unroll
            for (int nt=0;nt<8;nt++){
                int l = nt*8 + lc;
                Qs[o*68 + l]       = geluf(acc[mt][nt][0] + bva);
                Qs[o*68 + l + 1]   = geluf(acc[mt][nt][1] + bva);
                Qs[(o+8)*68 + l]   = geluf(acc[mt][nt][2] + bvb);
                Qs[(o+8)*68 + l+1] = geluf(acc[mt][nt][3] + bvb);
            }
        }
        __syncthreads();
        {
            int l = tid & 63, hb = (tid >> 6) * 4;
            #pragma unroll
            for (int hh=0;hh<4;hh++){
                int h = hb + hh;
                float qv[16], mx = -1e30f;
                #pragma unroll
                for (int d=0;d<16;d++){ qv[d] = Qs[(h*16+d)*68 + l]; mx = fmaxf(mx, qv[d]); }
                float s = 0.f;
                #pragma unroll
                for (int d=0;d<16;d++){ qv[d] = __expf(qv[d] - mx); s += qv[d]; }
                float is = 1.f / s;
                const float* kvh = kvs + h*256;
                float av[16];
                #pragma unroll
                for (int e=0;e<16;e++) av[e] = 0.f;
                #pragma unroll
                for (int d=0;d<16;d++){
                    float q = qv[d];
                    #pragma unroll
                    for (int e=0;e<16;e++) av[e] += q * kvh[d*16 + e];
                }
                #pragma unroll
                for (int e=0;e<16;e++) Qs[(h*16+e)*68 + l] = av[e] * is;
            }
        }
        __syncthreads();
        const float* xb = xb0 + l0;
        float*       zb = zb0 + l0;
        #pragma unroll 4
        for (int i=0;i<64;i++){
            int e = i*128 + tid;
            int c = e >> 6, lcc = e & 63;
            float att = Qs[c*68 + lcc];
            float zv = w0*att + w1*xb[(size_t)c*LL + lcc];
            zb[(size_t)c*LL + lcc] = zv;
            Qs[c*68 + lcc] = zv;
        }
        __syncthreads();
        #pragma unroll 8
        for (int j=0;j<64;j++){ float v = Qs[tid*68 + j]; zs += v; zs2 += v*v; }
    }
    atomicAdd(&g_stats[6*CC + tid], (double)zs);
    atomicAdd(&g_stats[7*CC + tid], (double)zs2);
}

// ------------------- per-row max + sum(exp) of k -------------------
__global__ void K_krow(){
    int row = blockIdx.x;
    const float* p = g_k + (size_t)row*LK;
    int tid = threadIdx.x, w = tid >> 5, ln = tid & 31;
    float vals[16], m = -1e30f;
    #pragma unroll
    for (int i=0;i<16;i++){ vals[i] = p[i*256 + tid]; m = fmaxf(m, vals[i]); }
    #pragma unroll
    for (int o=16;o>0;o>>=1) m = fmaxf(m, __shfl_xor_sync(0xffffffffu, m, o));
    __shared__ float rm[8], rs[8];
    if (ln == 0) rm[w] = m;
    __syncthreads();
    float bm = rm[0];
    #pragma unroll
    for (int i=1;i<8;i++) bm = fmaxf(bm, rm[i]);
    float s = 0.f;
    #pragma unroll
    for (int i=0;i<16;i++) s += __expf(vals[i] - bm);
    s = warpRedSum(s);
    if (ln == 0) rs[w] = s;
    __syncthreads();
    if (tid == 0){
        float tot = 0.f;
        #pragma unroll
        for (int i=0;i<8;i++) tot += rs[i];
        g_km[row]  = bm;
        g_kis[row] = 1.f / tot;
    }
}

// ------------------- kv = softmax_n(k)^T @ v per (b,h) -------------------
__global__ void K_kv(){
    __shared__ float ks[16*257], vs[16*257];
    __shared__ float mrow[16], isrow[16];
    int bh = blockIdx.x; int b = bh >> 3, h = bh & 7;
    int tid = threadIdx.x; int d = tid >> 4, e = tid & 15;
    const float* kb = g_k + ((size_t)b*CC + h*16)*LK;
    const float* vb = g_v + ((size_t)b*CC + h*16)*LK;
    if (tid < 16){
        mrow[tid]  = g_km [b*CC + h*16 + tid];
        isrow[tid] = g_kis[b*CC + h*16 + tid];
    }
    __syncthreads();
    float acc = 0.f;
    for (int n0=0;n0<LK;n0+=256){
        __syncthreads();
        #pragma unroll
        for (int i=0;i<16;i++){
            ks[i*257 + tid] = __expf(kb[(size_t)i*LK + n0 + tid] - mrow[i]) * isrow[i];
            vs[i*257 + tid] = vb[(size_t)i*LK + n0 + tid];
        }
        __syncthreads();
        #pragma unroll 8
        for (int j=0;j<256;j++)
            acc += ks[d*257 + j] * vs[e*257 + j];
    }
    g_kv[((size_t)bh*16 + d)*16 + e] = acc;
}

// ------------------- BN1d affine coefficients -------------------
__global__ void K_bnaff(int sel, const float* __restrict__ g, const float* __restrict__ bt){
    int t = threadIdx.x;
    int slot = sel ? 8 : 6;
    double cnt = (double)BB * (double)LL;
    double m = g_stats[(size_t)slot*CC + t] / cnt;
    double v = g_stats[(size_t)(slot+1)*CC + t] / cnt - m*m;
    float a = g[t] * rsqrtf((float)v + 1e-5f);
    float bc = bt[t] - (float)m * a;
    if (sel){ g_A2[t] = a; g_B2[t] = bc; }
    else    { g_A1[t] = a; g_B1[t] = bc; }
}

// ------------------- FFN via tensor cores + fused residual + pre-stats -------------------
// grid (LL/256, B); block 128; 4 tiles of 64 tokens.
__global__ void K_ffnT(const float* __restrict__ b1, const float* __restrict__ b2,
                       const float* __restrict__ fw){
    extern __shared__ char sm[];
    float* sA1 = (float*)(sm + FO_MISC);
    float* sB1 = sA1 + 128;
    float* sb1 = sB1 + 128;
    float* sb2 = sb1 + 32;
    int tid = threadIdx.x, lane = tid & 31, w = tid >> 5;
    int b = blockIdx.y, base_l = blockIdx.x*256;
    uint32_t sbase = s2u(sm);
    if (tid < 128){ sA1[tid] = g_A1[tid]; sB1[tid] = g_B1[tid]; sb2[tid] = b2[tid]; }
    if (tid < 32) sb1[tid] = b1[tid];
    // stage W1^T (32 rows x 128 k), 256B rows
    {
        const uint32_t* wh = (const uint32_t*)g_w1h;
        const uint32_t* wl = (const uint32_t*)g_w1l;
        #pragma unroll
        for (int i=0;i<16;i++){
            int e = i*128 + tid;
            int r = e >> 6, kp = e & 63;
            uint32_t off = (uint32_t)(r*256 + (((kp>>2) ^ (r&7))<<4) + ((kp&3)<<2));
            *(uint32_t*)(sm + FO_W1  + off) = wh[e];
            *(uint32_t*)(sm + FO_W1L + off) = wl[e];
        }
    }
    // stage W2^T (128 rows x 32 k), 128B rows
    {
        const uint32_t* wh = (const uint32_t*)g_w2h;
        const uint32_t* wl = (const uint32_t*)g_w2l;
        #pragma unroll
        for (int i=0;i<16;i++){
            int e = i*128 + tid;
            int r = e >> 4, kp = e & 15;
            uint32_t off = (uint32_t)(r*128 + (((kp>>2) ^ (r&3))<<4) + ((kp&3)<<2));
            *(uint32_t*)(sm + FO_W2  + off) = wh[e];
            *(uint32_t*)(sm + FO_W2L + off) = wl[e];
        }
    }
    __syncthreads();
    float a0 = fmaxf(fw[0], 0.f), a1 = fmaxf(fw[1], 0.f);
    float inv = 1.f / (a0 + a1 + 1e-12f);
    float w0 = a0*inv, w1 = a1*inv;
    const float* zb0 = g_z   + (size_t)b*CC*LL;
    float*       pb0 = g_pre + (size_t)b*CC*LL;
    int m = lane >> 3, li = lane & 7, chalf = m >> 1;
    int q = lane >> 2, lc = 2*(lane & 3);
    float stS[4] = {0.f,0.f,0.f,0.f}, stS2[4] = {0.f,0.f,0.f,0.f};
    for (int it=0; it<4; it++){
        int l0 = base_l + it*64;
        __syncthreads();
        // stage zin = A1*z + B1 as bf16 split, [l rows][c k-cols]
        {
            const float* zt = zb0 + l0;
            #pragma unroll
            for (int i=0;i<32;i++){
                int e = i*128 + tid;
                int l = e & 63, kp = e >> 6;
                int c0 = 2*kp, c1 = c0 + 1;
                float x0 = sA1[c0]*zt[(size_t)c0*LL + l] + sB1[c0];
                float x1 = sA1[c1]*zt[(size_t)c1*LL + l] + sB1[c1];
                __nv_bfloat16 h0 = __float2bfloat16_rn(x0);
                __nv_bfloat16 h1 = __float2bfloat16_rn(x1);
                __nv_bfloat16 q0 = __float2bfloat16_rn(x0 - __bfloat162float(h0));
                __nv_bfloat16 q1 = __float2bfloat16_rn(x1 - __bfloat162float(h1));
                uint32_t hp = (uint32_t)__bfloat16_as_ushort(h0) | ((uint32_t)__bfloat16_as_ushort(h1)<<16);
                uint32_t lp = (uint32_t)__bfloat16_as_ushort(q0) | ((uint32_t)__bfloat16_as_ushort(q1)<<16);
                uint32_t off = (uint32_t)(l*256 + (((kp>>2) ^ (l&7))<<4) + ((kp&3)<<2));
                *(uint32_t*)(sm + FO_Z  + off) = hp;
                *(uint32_t*)(sm + FO_ZL + off) = lp;
            }
        }
        __syncthreads();
        // GEMM1: warp w -> tokens [16w,16w+16), f rows 0..31, K=128
        float acc1[2][2][4];
        #pragma unroll
        for (int mt=0;mt<2;mt++)
            #pragma unroll
            for (int ng=0;ng<2;ng++)
                #pragma unroll
                for (int r=0;r<4;r++) acc1[mt][ng][r] = 0.f;
        #pragma unroll
        for (int ks=0; ks<8; ks++){
            int c = 2*ks + chalf;
            uint32_t ah[2][4], al[2][4];
            #pragma unroll
            for (int mt=0; mt<2; mt++){
                int row = mt*16 + (m&1)*8 + li;
                uint32_t adr = sbase + FO_W1 + (uint32_t)(row*256 + ((c ^ (row&7))<<4));
                LDM4(ah[mt][0],ah[mt][1],ah[mt][2],ah[mt][3], adr);
                LDM4(al[mt][0],al[mt][1],al[mt][2],al[mt][3], adr + (FO_W1L - FO_W1));
            }
            int brow = 16*w + (m&1)*8 + li;
            uint32_t badr = sbase + FO_Z + (uint32_t)(brow*256 + ((c ^ (brow&7))<<4));
            uint32_t bh[4], bl[4];
            LDM4(bh[0],bh[1],bh[2],bh[3], badr);
            LDM4(bl[0],bl[1],bl[2],bl[3], badr + (FO_ZL - FO_Z));
            #pragma unroll
            for (int mt=0; mt<2; mt++){
                MMAB(acc1[mt][0], ah[mt], bh[0], bh[2]);
                MMAB(acc1[mt][0], ah[mt], bl[0], bl[2]);
                MMAB(acc1[mt][0], al[mt], bh[0], bh[2]);
                MMAB(acc1[mt][1], ah[mt], bh[1], bh[3]);
                MMAB(acc1[mt][1], ah[mt], bl[1], bl[3]);
                MMAB(acc1[mt][1], al[mt], bh[1], bh[3]);
            }
        }
        __syncthreads();   // previous-tile H fully consumed before rewrite
        // h = gelu(acc1 + b1) -> stage H [l rows][f k-cols] bf16 split
        #pragma unroll
        for (int mt=0; mt<2; mt++){
            int fA = mt*16 + q, fB = fA + 8;
            #pragma unroll
            for (int ng=0; ng<2; ng++){
                int l = 16*w + ng*8 + lc;
                float vals[4];
                vals[0] = geluf(acc1[mt][ng][0] + sb1[fA]);
                vals[1] = geluf(acc1[mt][ng][1] + sb1[fA]);
                vals[2] = geluf(acc1[mt][ng][2] + sb1[fB]);
                vals[3] = geluf(acc1[mt][ng][3] + sb1[fB]);
                #pragma unroll
                for (int j=0;j<4;j++){
                    int ff = (j<2) ? fA : fB;
                    int ll = l + (j&1);
                    __nv_bfloat16 hi = __float2bfloat16_rn(vals[j]);
                    __nv_bfloat16 lo = __float2bfloat16_rn(vals[j] - __bfloat162float(hi));
                    uint32_t off = (uint32_t)(ll*128 + (((ff>>3) ^ (ll&3))<<4) + ((ff&7)<<1));
                    *(unsigned short*)(sm + FO_H  + off) = __bfloat16_as_ushort(hi);
                    *(unsigned short*)(sm + FO_HL + off) = __bfloat16_as_ushort(lo);
                }
            }
        }
        __syncthreads();
        // GEMM2: warp w -> o rows [32w,32w+32), all 64 tokens, K=32
        float acc2[2][8][4];
        #pragma unroll
        for (int mt=0;mt<2;mt++)
            #pragma unroll
            for (int nt=0;nt<8;nt++)
                #pragma unroll
                for (int r=0;r<4;r++) acc2[mt][nt][r] = 0.f;
        #pragma unroll
        for (int s=0; s<2; s++){
            int c = 2*s + chalf;
            uint32_t ah[2][4], al[2][4];
            #pragma unroll
            for (int mt=0; mt<2; mt++){
                int row = w*32 + mt*16 + (m&1)*8 + li;
                uint32_t adr = sbase + FO_W2 + (uint32_t)(row*128 + ((c ^ (row&3))<<4));
                LDM4(ah[mt][0],ah[mt][1],ah[mt][2],ah[mt][3], adr);
                LDM4(al[mt][0],al[mt][1],al[mt][2],al[mt][3], adr + (FO_W2L - FO_W2));
            }
            #pragma unroll
            for (int nb=0; nb<4; nb++){
                int brow = nb*16 + (m&1)*8 + li;
                uint32_t badr = sbase + FO_H + (uint32_t)(brow*128 + ((c ^ (brow&3))<<4));
                uint32_t bh[4], bl[4];
                LDM4(bh[0],bh[1],bh[2],bh[3], badr);
                LDM4(bl[0],bl[1],bl[2],bl[3], badr + (FO_HL - FO_H));
                #pragma unroll
                for (int mt=0; mt<2; mt++){
                    MMAB(acc2[mt][2*nb],   ah[mt], bh[0], bh[2]);
                    MMAB(acc2[mt][2*nb],   ah[mt], bl[0], bl[2]);
                    MMAB(acc2[mt][2*nb],   al[mt], bh[0], bh[2]);
                    MMAB(acc2[mt][2*nb+1], ah[mt], bh[1], bh[3]);
                    MMAB(acc2[mt][2*nb+1], ah[mt], bl[1], bl[3]);
                    MMAB(acc2[mt][2*nb+1], al[mt], bh[1], bh[3]);
                }
            }
        }
        // epilogue: gelu + residual(zin from smem) + write g_pre + stats
        #pragma unroll
        for (int mt=0; mt<2; mt++){
            int oA = w*32 + mt*16 + q, oB = oA + 8;
            float bvA = sb2[oA], bvB = sb2[oB];
            #pragma unroll
            for (int nt=0; nt<8; nt++){
                int l = nt*8 + lc;
                float pr[4];
                #pragma unroll
                for (int j=0;j<4;j++){
                    int o  = (j<2) ? oA : oB;
                    int ll = l + (j&1);
                    float y = geluf(acc2[mt][nt][j] + ((j<2)?bvA:bvB));
                    uint32_t off = (uint32_t)(ll*256 + (((o>>3) ^ (ll&7))<<4) + ((o&7)<<1));
                    float zh = __bfloat162float(__ushort_as_bfloat16(*(unsigned short*)(sm + FO_Z  + off)));
                    float zl = __bfloat162float(__ushort_as_bfloat16(*(unsigned short*)(sm + FO_ZL + off)));
                    float zin = zh + zl;
                    pr[j] = w0*y + w1*zin;
                    int sidx = mt*2 + (j>>1);
                    stS[sidx]  += pr[j];
                    stS2[sidx] += pr[j]*pr[j];
                }
                *(float2*)&pb0[(size_t)oA*LL + l0 + l] = make_float2(pr[0], pr[1]);
                *(float2*)&pb0[(size_t)oB*LL + l0 + l] = make_float2(pr[2], pr[3]);
            }
        }
    }
    // stats: quad-reduce (cols) then atomics by quad leader
    #pragma unroll
    for (int j=0;j<4;j++){
        float s = stS[j], s2 = stS2[j];
        s  += __shfl_xor_sync(0xffffffffu, s, 1);
        s  += __shfl_xor_sync(0xffffffffu, s, 2);
        s2 += __shfl_xor_sync(0xffffffffu, s2, 1);
        s2 += __shfl_xor_sync(0xffffffffu, s2, 2);
        if ((lane & 3) == 0){
            int o = w*32 + (j>>1)*16 + q + (j&1)*8;
            atomicAdd(&g_stats[8*CC + o], (double)s);
            atomicAdd(&g_stats[9*CC + o], (double)s2);
        }
    }
}

// ------------------- final BN affine -> d_out -------------------
__global__ void K_final(float* __restrict__ out){
    size_t i = ((size_t)blockIdx.x*256 + threadIdx.x)*4;
    int c = (int)((i >> 14) & 127);
    float4 v = *(const float4*)&g_pre[i];
    float A = g_A2[c], Bc = g_B2[c];
    float4 r;
    r.x = A*v.x + Bc; r.y = A*v.y + Bc; r.z = A*v.z + Bc; r.w = A*v.w + Bc;
    *(float4*)&out[i] = r;
}

// ------------------- launch -------------------
extern "C" void kernel_launch(void* const* d_in, const int* in_sizes, int n_in,
                              void* d_out, int out_size){
    const float* x         = (const float*)d_in[0];
    const float* dw_w      = (const float*)d_in[1];
    const float* bn2_g     = (const float*)d_in[2];
    const float* bn2_b     = (const float*)d_in[3];
    const float* pw_w      = (const float*)d_in[4];
    const float* pw_b      = (const float*)d_in[5];
    const float* add_w     = (const float*)d_in[6];
    const float* bn1_g     = (const float*)d_in[7];
    const float* bn1_b     = (const float*)d_in[8];
    const float* W1        = (const float*)d_in[9];
    const float* b1        = (const float*)d_in[10];
    const float* W2        = (const float*)d_in[11];
    const float* b2        = (const float*)d_in[12];
    const float* ffn_add_w = (const float*)d_in[13];
    const float* ffn_bn_g  = (const float*)d_in[14];
    const float* ffn_bn_b  = (const float*)d_in[15];
    float* out = (float*)d_out;

    cudaFuncSetAttribute(K_pwkvT,  cudaFuncAttributeMaxDynamicSharedMemorySize, PWKV_SMEM);
    cudaFuncSetAttribute(K_pwattT, cudaFuncAttributeMaxDynamicSharedMemorySize, PWATT_SMEM);
    cudaFuncSetAttribute(K_ffnT,   cudaFuncAttributeMaxDynamicSharedMemorySize, FFN_SMEM);

    K_zero<<<5,256>>>();
    K_dw<<<dim3(2,CC,BB),256>>>(x, dw_w);
    K_prep<<<1,128>>>(bn2_g, bn2_b, pw_w, pw_b, W1, W2);
    K_pwkvT<<<dim3(LK/256,BB,2),128,PWKV_SMEM>>>();
    K_krow<<<BB*CC,256>>>();
    K_kv<<<BB*NH,256>>>();
    K_pwattT<<<dim3(LL/256,BB),128,PWATT_SMEM>>>(x, add_w);
    K_bnaff<<<1,128>>>(0, bn1_g, bn1_b);
    K_ffnT<<<dim3(LL/256,BB),128,FFN_SMEM>>>(b1, b2, ffn_add_w);
    K_bnaff<<<1,128>>>(1, ffn_bn_g, ffn_bn_b);
    K_final<<<(BB*CC*LL)/(256*4),256>>>(out);
}

// round 16
// speedup vs baseline: 1.9282x; 1.1739x over previous
#include <cuda_runtime.h>
#include <cuda_bf16.h>
#include <cstdint>
#include <math.h>

#define BB 16
#define CC 128
#define LL 16384
#define LK 4096
#define NH 8
#define DH 16

typedef unsigned long long ull;

// ------------------- scratch (device globals; no allocations) -------------------
__device__ float g_dwq[BB*CC*LL];
__device__ float g_dwk[BB*CC*LK];
__device__ float g_dwv[BB*CC*LK];
__device__ float g_k  [BB*CC*LK];
__device__ float g_v  [BB*CC*LK];
__device__ float g_z  [BB*CC*LL];
__device__ float g_pre[BB*CC*LL];
__device__ float g_kv [BB*NH*DH*DH];
__device__ float g_km [BB*CC];
__device__ float g_kis[BB*CC];
__device__ __align__(16) __nv_bfloat16 g_whi[3*CC*CC];
__device__ __align__(16) __nv_bfloat16 g_wlo[3*CC*CC];
__device__ __align__(16) __nv_bfloat16 g_w1h[32*CC];
__device__ __align__(16) __nv_bfloat16 g_w1l[32*CC];
__device__ __align__(16) __nv_bfloat16 g_w2h[CC*32];
__device__ __align__(16) __nv_bfloat16 g_w2l[CC*32];
__device__ float g_beff[3*CC];
__device__ float g_A1[CC], g_B1[CC], g_A2[CC], g_B2[CC];
// slots: 0/1 dwq, 2/3 dwk, 4/5 dwv, 6/7 z, 8/9 pre
__device__ double g_stats[10*CC];

// ------------------- helpers -------------------
__device__ __forceinline__ float geluf(float x){
    return 0.5f * x * (1.0f + erff(x * 0.70710678118654752440f));
}
__device__ __forceinline__ float warpRedSum(float v){
    v += __shfl_xor_sync(0xffffffffu, v, 16);
    v += __shfl_xor_sync(0xffffffffu, v, 8);
    v += __shfl_xor_sync(0xffffffffu, v, 4);
    v += __shfl_xor_sync(0xffffffffu, v, 2);
    v += __shfl_xor_sync(0xffffffffu, v, 1);
    return v;
}
__device__ __forceinline__ void blockAccum(float v, double* dst, float* red){
    v = warpRedSum(v);
    int w = threadIdx.x >> 5, ln = threadIdx.x & 31;
    if (ln == 0) red[w] = v;
    __syncthreads();
    if (threadIdx.x == 0){
        float s = 0.f;
        #pragma unroll
        for (int i=0;i<8;i++) s += red[i];
        atomicAdd(dst, (double)s);
    }
    __syncthreads();
}
__device__ __forceinline__ uint32_t s2u(const void* p){
    uint32_t a;
    asm("{ .reg .u64 t; cvta.to.shared.u64 t, %1; cvt.u32.u64 %0, t; }" : "=r"(a) : "l"(p));
    return a;
}

// ------------------- warp-MMA primitives (portable PTX, sm_80+) -------------------
#define LDM4(r0,r1,r2,r3, adr) \
    asm volatile("ldmatrix.sync.aligned.m8n8.x4.shared.b16 {%0,%1,%2,%3}, [%4];" \
        : "=r"(r0), "=r"(r1), "=r"(r2), "=r"(r3) : "r"(adr))

#define MMAB(d, a, b0, b1) \
    asm volatile("mma.sync.aligned.m16n8k16.row.col.f32.bf16.bf16.f32 " \
        "{%0,%1,%2,%3}, {%4,%5,%6,%7}, {%8,%9}, {%0,%1,%2,%3};" \
        : "+f"((d)[0]), "+f"((d)[1]), "+f"((d)[2]), "+f"((d)[3]) \
        : "r"((a)[0]), "r"((a)[1]), "r"((a)[2]), "r"((a)[3]), "r"(b0), "r"(b1))

// pw smem layout (bytes)
#define OFF_WL 32768
#define OFF_X  65536
#define OFF_XL 16384
#define PWKV_SMEM  98304
#define OFF_KV2 100352
#define PWATT_SMEM 108544

// FFN smem layout (bytes)
#define FO_W1  0
#define FO_W1L 8192
#define FO_Z   16384
#define FO_ZL  32768
#define FO_W2  49152
#define FO_W2L 65536
#define FO_H   81920
#define FO_HL  90112
#define FO_MISC 98304
#define FFN_SMEM 100352

// ------------------- zero stats + kv -------------------
__global__ void K_zero(){
    int i = blockIdx.x*256 + threadIdx.x;
    if (i < 10*CC) g_stats[i] = 0.0;
    if (i < BB*NH*DH*DH) g_kv[i] = 0.f;
}

// ------------------- depthwise 3x3, 3 branches + fused BN stats -------------------
__global__ void K_dw(const float* __restrict__ x, const float* __restrict__ dw_w){
    __shared__ float im[66*128];
    __shared__ float red[8];
    int r0 = blockIdx.x*64, c = blockIdx.y, b = blockIdx.z;
    int tid = threadIdx.x;
    const float* xc = x + ((size_t)b*CC + c)*LL;
    #pragma unroll
    for (int i=0;i<33;i++){
        int e = i*256 + tid;
        int rr = e >> 7, w = e & 127;
        int gr = r0 - 1 + rr;
        im[e] = (gr >= 0 && gr < 128) ? xc[gr*128 + w] : 0.0f;
    }
    float wq[9], wk[9], wv[9];
    #pragma unroll
    for (int k=0;k<9;k++){
        wq[k] = dw_w[c*9 + k];
        wk[k] = dw_w[(CC   + c)*9 + k];
        wv[k] = dw_w[(2*CC + c)*9 + k];
    }
    __syncthreads();
    float sq=0.f, sq2=0.f, sk=0.f, sk2=0.f, sv=0.f, sv2=0.f;
    float* outq = g_dwq + ((size_t)b*CC + c)*LL + r0*128;
    #pragma unroll 2
    for (int i=0;i<32;i++){
        int s = i*256 + tid;
        int hl = s >> 7, w = s & 127;
        float acc = 0.f;
        #pragma unroll
        for (int ky=0;ky<3;ky++){
            const float* row = im + (hl+ky)*128 + w;
            if (w > 0)   acc += wq[ky*3+0] * row[-1];
                         acc += wq[ky*3+1] * row[0];
            if (w < 127) acc += wq[ky*3+2] * row[1];
        }
        outq[s] = acc;
        sq += acc; sq2 += acc*acc;
    }
    float* outk = g_dwk + ((size_t)b*CC + c)*LK + (r0>>1)*64;
    float* outv = g_dwv + ((size_t)b*CC + c)*LK + (r0>>1)*64;
    #pragma unroll
    for (int i=0;i<8;i++){
        int s = i*256 + tid;
        int ho = s >> 6, wo = s & 63;
        float ak = 0.f, av = 0.f;
        #pragma unroll
        for (int ky=0;ky<3;ky++){
            const float* row = im + (2*ho+ky)*128 + 2*wo;
            if (wo > 0){ ak += wk[ky*3+0]*row[-1]; av += wv[ky*3+0]*row[-1]; }
            ak += wk[ky*3+1]*row[0]; av += wv[ky*3+1]*row[0];
            ak += wk[ky*3+2]*row[1]; av += wv[ky*3+2]*row[1];
        }
        outk[s] = ak; outv[s] = av;
        sk += ak; sk2 += ak*ak; sv += av; sv2 += av*av;
    }
    __syncthreads();
    blockAccum(sq,  &g_stats[0*CC + c], red);
    blockAccum(sq2, &g_stats[1*CC + c], red);
    blockAccum(sk,  &g_stats[2*CC + c], red);
    blockAccum(sk2, &g_stats[3*CC + c], red);
    blockAccum(sv,  &g_stats[4*CC + c], red);
    blockAccum(sv2, &g_stats[5*CC + c], red);
}

// ------------------- fold BN2d into pointwise weights + all bf16 splits -------------------
__global__ void K_prep(const float* __restrict__ bn2_g, const float* __restrict__ bn2_b,
                       const float* __restrict__ pw_w, const float* __restrict__ pw_b,
                       const float* __restrict__ W1, const float* __restrict__ W2){
    __shared__ float alpha[CC], beta[CC];
    int t = threadIdx.x;  // 128
    for (int i=0;i<3;i++){
        double cnt = (i==0) ? (double)BB*(double)LL : (double)BB*(double)LK;
        double m = g_stats[(size_t)(2*i)*CC + t] / cnt;
        double v = g_stats[(size_t)(2*i+1)*CC + t] / cnt - m*m;
        float A = bn2_g[i*CC + t] * rsqrtf((float)v + 1e-5f);
        alpha[t] = A;
        beta[t]  = bn2_b[i*CC + t] - (float)m * A;
        __syncthreads();
        float acc = pw_b[i*CC + t];
        const float* wrow = pw_w + (size_t)(i*CC + t)*CC;
        __nv_bfloat16* whrow = g_whi + (size_t)(i*CC + t)*CC;
        __nv_bfloat16* wlrow = g_wlo + (size_t)(i*CC + t)*CC;
        for (int c2=0;c2<CC;c2++){
            float w = wrow[c2];
            float we = w * alpha[c2];
            __nv_bfloat16 hi = __float2bfloat16_rn(we);
            whrow[c2] = hi;
            wlrow[c2] = __float2bfloat16_rn(we - __bfloat162float(hi));
            acc += w * beta[c2];
        }
        g_beff[i*CC + t] = acc;
        __syncthreads();
    }
    for (int f=0; f<32; f++){
        float w = W1[t*32 + f];
        __nv_bfloat16 hi = __float2bfloat16_rn(w);
        g_w1h[f*CC + t] = hi;
        g_w1l[f*CC + t] = __float2bfloat16_rn(w - __bfloat162float(hi));
    }
    for (int f=0; f<32; f++){
        float w = W2[f*CC + t];
        __nv_bfloat16 hi = __float2bfloat16_rn(w);
        g_w2h[t*32 + f] = hi;
        g_w2l[t*32 + f] = __float2bfloat16_rn(w - __bfloat162float(hi));
    }
}

// ------------------- staging (256-thread variants) -------------------
__device__ __forceinline__ void stageW256(char* sm, int which, int tid){
    const uint32_t* wh = (const uint32_t*)(g_whi + (size_t)which*CC*CC);
    const uint32_t* wl = (const uint32_t*)(g_wlo + (size_t)which*CC*CC);
    #pragma unroll
    for (int i=0;i<32;i++){
        int e = i*256 + tid;
        int o = e >> 6, kp = e & 63;
        uint32_t off = (uint32_t)(o*256 + ((((kp>>2) ^ (o&7)))<<4) + ((kp&3)<<2));
        *(uint32_t*)(sm + off)          = wh[o*64 + kp];
        *(uint32_t*)(sm + OFF_WL + off) = wl[o*64 + kp];
    }
}
__device__ __forceinline__ void stageX256(char* sm, const float* sp, int Ls, int tid){
    #pragma unroll
    for (int i=0;i<16;i++){
        int e = i*256 + tid;
        int l = e & 63, kp = e >> 6;
        float x0 = sp[(size_t)(2*kp)  *Ls + l];
        float x1 = sp[(size_t)(2*kp+1)*Ls + l];
        __nv_bfloat16 h0 = __float2bfloat16_rn(x0);
        __nv_bfloat16 h1 = __float2bfloat16_rn(x1);
        __nv_bfloat16 q0 = __float2bfloat16_rn(x0 - __bfloat162float(h0));
        __nv_bfloat16 q1 = __float2bfloat16_rn(x1 - __bfloat162float(h1));
        uint32_t hp = (uint32_t)__bfloat16_as_ushort(h0) | ((uint32_t)__bfloat16_as_ushort(h1)<<16);
        uint32_t lp = (uint32_t)__bfloat16_as_ushort(q0) | ((uint32_t)__bfloat16_as_ushort(q1)<<16);
        uint32_t off = (uint32_t)(l*256 + ((((kp>>2) ^ (l&7)))<<4) + ((kp&3)<<2));
        *(uint32_t*)(sm + OFF_X + off)          = hp;
        *(uint32_t*)(sm + OFF_X + OFF_XL + off) = lp;
    }
}

// ------------------- warp-MMA GEMM: 8 warps, warp owns 16 o-rows x 64 l -------------------
__device__ __forceinline__ void gemmMMA256(char* sm, int tid, float acc[8][4]){
    int lane = tid & 31, w = tid >> 5;
    int m = lane >> 3, li = lane & 7;
    uint32_t sb = s2u(sm);
    int arow = w*16 + (m&1)*8 + li;
    int brow0 = (m&1)*8 + li;
    int chalf = m >> 1;
    #pragma unroll
    for (int ks=0; ks<8; ks++){
        int c = 2*ks + chalf;
        uint32_t ah[4], al[4];
        uint32_t adr = sb + (uint32_t)(arow*256 + ((c ^ (arow&7))<<4));
        LDM4(ah[0],ah[1],ah[2],ah[3], adr);
        LDM4(al[0],al[1],al[2],al[3], adr + OFF_WL);
        #pragma unroll
        for (int nb=0; nb<4; nb++){
            int row = nb*16 + brow0;
            uint32_t badr = sb + OFF_X + (uint32_t)(row*256 + ((c ^ (row&7))<<4));
            uint32_t bh[4], bl[4];
            LDM4(bh[0],bh[1],bh[2],bh[3], badr);
            LDM4(bl[0],bl[1],bl[2],bl[3], badr + OFF_XL);
            MMAB(acc[2*nb],   ah, bh[0], bh[2]);
            MMAB(acc[2*nb],   ah, bl[0], bl[2]);
            MMAB(acc[2*nb],   al, bh[0], bh[2]);
            MMAB(acc[2*nb+1], ah, bh[1], bh[3]);
            MMAB(acc[2*nb+1], ah, bl[1], bl[3]);
            MMAB(acc[2*nb+1], al, bh[1], bh[3]);
        }
    }
}

// ------------------- pointwise GEMM for k/v (tensor cores, 256 thr) -------------------
__global__ void K_pwkvT(){
    extern __shared__ char sm[];
    int which = blockIdx.z + 1;
    const float* src  = (which==1) ? g_dwk : g_dwv;
    float*       dst  = (which==1) ? g_k   : g_v;
    const float* bias = g_beff + which*CC;
    int tid = threadIdx.x, lane = tid & 31, w = tid >> 5;
    int b = blockIdx.y, base_l = blockIdx.x*256;
    stageW256(sm, which, tid);
    const float* srcb = src + (size_t)b*CC*LK;
    float*       dstb = dst + (size_t)b*CC*LK;
    int o0 = w*16 + (lane>>2), lc = 2*(lane&3);
    for (int it=0; it<4; it++){
        int l0 = base_l + it*64;
        __syncthreads();
        stageX256(sm, srcb + l0, LK, tid);
        __syncthreads();
        float acc[8][4];
        #pragma unroll
        for (int nt=0;nt<8;nt++)
            #pragma unroll
            for (int r=0;r<4;r++) acc[nt][r] = 0.f;
        gemmMMA256(sm, tid, acc);
        float bva = bias[o0], bvb = bias[o0+8];
        #pragma unroll
        for (int nt=0;nt<8;nt++){
            int l = l0 + nt*8 + lc;
            float2 r0, r1;
            r0.x = geluf(acc[nt][0] + bva);
            r0.y = geluf(acc[nt][1] + bva);
            r1.x = geluf(acc[nt][2] + bvb);
            r1.y = geluf(acc[nt][3] + bvb);
            *(float2*)&dstb[(size_t)o0*LK + l]     = r0;
            *(float2*)&dstb[(size_t)(o0+8)*LK + l] = r1;
        }
    }
}

// ------------------- q GEMM + GELU + attention + residual + z-stats (256 thr) -------------------
__global__ void K_pwattT(const float* __restrict__ x, const float* __restrict__ add_w){
    extern __shared__ char sm[];
    float* Qs  = (float*)(sm + OFF_X);
    float* kvs = (float*)(sm + OFF_KV2);
    int tid = threadIdx.x, lane = tid & 31, w = tid >> 5;
    int b = blockIdx.y, base_l = blockIdx.x*256;
    {
        const float* kvp = g_kv + (size_t)b*NH*DH*DH;
        for (int i=tid;i<NH*DH*DH;i+=256) kvs[i] = kvp[i];
    }
    stageW256(sm, 0, tid);
    float a0 = fmaxf(add_w[0], 0.f), a1 = fmaxf(add_w[1], 0.f);
    float inv = 1.f / (a0 + a1 + 1e-12f);
    float w0 = a0*inv, w1 = a1*inv;
    const float* srcb = g_dwq + (size_t)b*CC*LL;
    const float* xb0  = x     + (size_t)b*CC*LL;
    float*       zb0  = g_z   + (size_t)b*CC*LL;
    int o0 = w*16 + (lane>>2), lc = 2*(lane&3);
    float zs = 0.f, zs2 = 0.f;
    for (int it=0; it<4; it++){
        int l0 = base_l + it*64;
        __syncthreads();
        stageX256(sm, srcb + l0, LL, tid);
        __syncthreads();
        float acc[8][4];
        #pragma unroll
        for (int nt=0;nt<8;nt++)
            #pragma unroll
            for (int r=0;r<4;r++) acc[nt][r] = 0.f;
        gemmMMA256(sm, tid, acc);
        __syncthreads();   // all warps done reading X; Qs may overwrite it
        float bva = g_beff[o0], bvb = g_beff[o0+8];
        #pragma unroll
        for (int nt=0;nt<8;nt++){
            int l = nt*8 + lc;
            Qs[o0*68 + l]       = geluf(acc[nt][0] + bva);
            Qs[o0*68 + l + 1]   = geluf(acc[nt][1] + bva);
            Qs[(o0+8)*68 + l]   = geluf(acc[nt][2] + bvb);
            Qs[(o0+8)*68 + l+1] = geluf(acc[nt][3] + bvb);
        }
        __syncthreads();
        // attention: thread handles token l (64 tokens) for 2 heads
        {
            int l = tid & 63, hb = (tid >> 6) * 2;
            #pragma unroll
            for (int hh=0;hh<2;hh++){
                int h = hb + hh;
                float qv[16], mx = -1e30f;
                #pragma unroll
                for (int d=0;d<16;d++){ qv[d] = Qs[(h*16+d)*68 + l]; mx = fmaxf(mx, qv[d]); }
                float s = 0.f;
                #pragma unroll
                for (int d=0;d<16;d++){ qv[d] = __expf(qv[d] - mx); s += qv[d]; }
                float is = 1.f / s;
                const float* kvh = kvs + h*256;
                float av[16];
                #pragma unroll
                for (int e=0;e<16;e++) av[e] = 0.f;
                #pragma unroll
                for (int d=0;d<16;d++){
                    float q = qv[d];
                    #pragma unroll
                    for (int e=0;e<16;e++) av[e] += q * kvh[d*16 + e];
                }
                #pragma unroll
                for (int e=0;e<16;e++) Qs[(h*16+e)*68 + l] = av[e] * is;
            }
        }
        __syncthreads();
        // residual addw + writeout + keep z in Qs for stats
        const float* xb = xb0 + l0;
        float*       zb = zb0 + l0;
        #pragma unroll 4
        for (int i=0;i<32;i++){
            int e = i*256 + tid;
            int c = e >> 6, lcc = e & 63;
            float att = Qs[c*68 + lcc];
            float zv = w0*att + w1*xb[(size_t)c*LL + lcc];
            zb[(size_t)c*LL + lcc] = zv;
            Qs[c*68 + lcc] = zv;
        }
        __syncthreads();
        if (tid < 128){
            #pragma unroll 8
            for (int j=0;j<64;j++){ float v = Qs[tid*68 + j]; zs += v; zs2 += v*v; }
        }
        __syncthreads();
    }
    if (tid < 128){
        atomicAdd(&g_stats[6*CC + tid], (double)zs);
        atomicAdd(&g_stats[7*CC + tid], (double)zs2);
    }
}

// ------------------- per-row max + sum(exp) of k -------------------
__global__ void K_krow(){
    int row = blockIdx.x;
    const float* p = g_k + (size_t)row*LK;
    int tid = threadIdx.x, w = tid >> 5, ln = tid & 31;
    float vals[16], m = -1e30f;
    #pragma unroll
    for (int i=0;i<16;i++){ vals[i] = p[i*256 + tid]; m = fmaxf(m, vals[i]); }
    #pragma unroll
    for (int o=16;o>0;o>>=1) m = fmaxf(m, __shfl_xor_sync(0xffffffffu, m, o));
    __shared__ float rm[8], rs[8];
    if (ln == 0) rm[w] = m;
    __syncthreads();
    float bm = rm[0];
    #pragma unroll
    for (int i=1;i<8;i++) bm = fmaxf(bm, rm[i]);
    float s = 0.f;
    #pragma unroll
    for (int i=0;i<16;i++) s += __expf(vals[i] - bm);
    s = warpRedSum(s);
    if (ln == 0) rs[w] = s;
    __syncthreads();
    if (tid == 0){
        float tot = 0.f;
        #pragma unroll
        for (int i=0;i<8;i++) tot += rs[i];
        g_km[row]  = bm;
        g_kis[row] = 1.f / tot;
    }
}

// ------------------- kv partial: grid (B*H, 4), each block 1024 n's -------------------
__global__ void K_kv(){
    __shared__ float ks[16*257], vs[16*257];
    __shared__ float mrow[16], isrow[16];
    int bh = blockIdx.x; int b = bh >> 3, h = bh & 7;
    int part = blockIdx.y;
    int tid = threadIdx.x; int d = tid >> 4, e = tid & 15;
    const float* kb = g_k + ((size_t)b*CC + h*16)*LK;
    const float* vb = g_v + ((size_t)b*CC + h*16)*LK;
    if (tid < 16){
        mrow[tid]  = g_km [b*CC + h*16 + tid];
        isrow[tid] = g_kis[b*CC + h*16 + tid];
    }
    __syncthreads();
    float acc = 0.f;
    for (int n0=part*1024; n0<part*1024+1024; n0+=256){
        __syncthreads();
        #pragma unroll
        for (int i=0;i<16;i++){
            ks[i*257 + tid] = __expf(kb[(size_t)i*LK + n0 + tid] - mrow[i]) * isrow[i];
            vs[i*257 + tid] = vb[(size_t)i*LK + n0 + tid];
        }
        __syncthreads();
        #pragma unroll 8
        for (int j=0;j<256;j++)
            acc += ks[d*257 + j] * vs[e*257 + j];
    }
    atomicAdd(&g_kv[((size_t)bh*16 + d)*16 + e], acc);
}

// ------------------- BN1d affine coefficients -------------------
__global__ void K_bnaff(int sel, const float* __restrict__ g, const float* __restrict__ bt){
    int t = threadIdx.x;
    int slot = sel ? 8 : 6;
    double cnt = (double)BB * (double)LL;
    double m = g_stats[(size_t)slot*CC + t] / cnt;
    double v = g_stats[(size_t)(slot+1)*CC + t] / cnt - m*m;
    float a = g[t] * rsqrtf((float)v + 1e-5f);
    float bc = bt[t] - (float)m * a;
    if (sel){ g_A2[t] = a; g_B2[t] = bc; }
    else    { g_A1[t] = a; g_B1[t] = bc; }
}

// ------------------- FFN via tensor cores + fused residual + pre-stats -------------------
// grid (LL/256, B); block 128; 4 tiles of 64 tokens.
__global__ void K_ffnT(const float* __restrict__ b1, const float* __restrict__ b2,
                       const float* __restrict__ fw){
    extern __shared__ char sm[];
    float* sA1 = (float*)(sm + FO_MISC);
    float* sB1 = sA1 + 128;
    float* sb1 = sB1 + 128;
    float* sb2 = sb1 + 32;
    int tid = threadIdx.x, lane = tid & 31, w = tid >> 5;
    int b = blockIdx.y, base_l = blockIdx.x*256;
    uint32_t sbase = s2u(sm);
    if (tid < 128){ sA1[tid] = g_A1[tid]; sB1[tid] = g_B1[tid]; sb2[tid] = b2[tid]; }
    if (tid < 32) sb1[tid] = b1[tid];
    {
        const uint32_t* wh = (const uint32_t*)g_w1h;
        const uint32_t* wl = (const uint32_t*)g_w1l;
        #pragma unroll
        for (int i=0;i<16;i++){
            int e = i*128 + tid;
            int r = e >> 6, kp = e & 63;
            uint32_t off = (uint32_t)(r*256 + (((kp>>2) ^ (r&7))<<4) + ((kp&3)<<2));
            *(uint32_t*)(sm + FO_W1  + off) = wh[e];
            *(uint32_t*)(sm + FO_W1L + off) = wl[e];
        }
    }
    {
        const uint32_t* wh = (const uint32_t*)g_w2h;
        const uint32_t* wl = (const uint32_t*)g_w2l;
        #pragma unroll
        for (int i=0;i<16;i++){
            int e = i*128 + tid;
            int r = e >> 4, kp = e & 15;
            uint32_t off = (uint32_t)(r*128 + (((kp>>2) ^ (r&3))<<4) + ((kp&3)<<2));
            *(uint32_t*)(sm + FO_W2  + off) = wh[e];
            *(uint32_t*)(sm + FO_W2L + off) = wl[e];
        }
    }
    __syncthreads();
    float a0 = fmaxf(fw[0], 0.f), a1 = fmaxf(fw[1], 0.f);
    float inv = 1.f / (a0 + a1 + 1e-12f);
    float w0 = a0*inv, w1 = a1*inv;
    const float* zb0 = g_z   + (size_t)b*CC*LL;
    float*       pb0 = g_pre + (size_t)b*CC*LL;
    int m = lane >> 3, li = lane & 7, chalf = m >> 1;
    int q = lane >> 2, lc = 2*(lane & 3);
    float stS[4] = {0.f,0.f,0.f,0.f}, stS2[4] = {0.f,0.f,0.f,0.f};
    for (int it=0; it<4; it++){
        int l0 = base_l + it*64;
        __syncthreads();
        {
            const float* zt = zb0 + l0;
            #pragma unroll
            for (int i=0;i<32;i++){
                int e = i*128 + tid;
                int l = e & 63, kp = e >> 6;
                int c0 = 2*kp, c1 = c0 + 1;
                float x0 = sA1[c0]*zt[(size_t)c0*LL + l] + sB1[c0];
                float x1 = sA1[c1]*zt[(size_t)c1*LL + l] + sB1[c1];
                __nv_bfloat16 h0 = __float2bfloat16_rn(x0);
                __nv_bfloat16 h1 = __float2bfloat16_rn(x1);
                __nv_bfloat16 q0 = __float2bfloat16_rn(x0 - __bfloat162float(h0));
                __nv_bfloat16 q1 = __float2bfloat16_rn(x1 - __bfloat162float(h1));
                uint32_t hp = (uint32_t)__bfloat16_as_ushort(h0) | ((uint32_t)__bfloat16_as_ushort(h1)<<16);
                uint32_t lp = (uint32_t)__bfloat16_as_ushort(q0) | ((uint32_t)__bfloat16_as_ushort(q1)<<16);
                uint32_t off = (uint32_t)(l*256 + (((kp>>2) ^ (l&7))<<4) + ((kp&3)<<2));
                *(uint32_t*)(sm + FO_Z  + off) = hp;
                *(uint32_t*)(sm + FO_ZL + off) = lp;
            }
        }
        __syncthreads();
        float acc1[2][2][4];
        #pragma unroll
        for (int mt=0;mt<2;mt++)
            #pragma unroll
            for (int ng=0;ng<2;ng++)
                #pragma unroll
                for (int r=0;r<4;r++) acc1[mt][ng][r] = 0.f;
        #pragma unroll
        for (int ks=0; ks<8; ks++){
            int c = 2*ks + chalf;
            uint32_t ah[2][4], al[2][4];
            #pragma unroll
            for (int mt=0; mt<2; mt++){
                int row = mt*16 + (m&1)*8 + li;
                uint32_t adr = sbase + FO_W1 + (uint32_t)(row*256 + ((c ^ (row&7))<<4));
                LDM4(ah[mt][0],ah[mt][1],ah[mt][2],ah[mt][3], adr);
                LDM4(al[mt][0],al[mt][1],al[mt][2],al[mt][3], adr + (FO_W1L - FO_W1));
            }
            int brow = 16*w + (m&1)*8 + li;
            uint32_t badr = sbase + FO_Z + (uint32_t)(brow*256 + ((c ^ (brow&7))<<4));
            uint32_t bh[4], bl[4];
            LDM4(bh[0],bh[1],bh[2],bh[3], badr);
            LDM4(bl[0],bl[1],bl[2],bl[3], badr + (FO_ZL - FO_Z));
            #pragma unroll
            for (int mt=0; mt<2; mt++){
                MMAB(acc1[mt][0], ah[mt], bh[0], bh[2]);
                MMAB(acc1[mt][0], ah[mt], bl[0], bl[2]);
                MMAB(acc1[mt][0], al[mt], bh[0], bh[2]);
                MMAB(acc1[mt][1], ah[mt], bh[1], bh[3]);
                MMAB(acc1[mt][1], ah[mt], bl[1], bl[3]);
                MMAB(acc1[mt][1], al[mt], bh[1], bh[3]);
            }
        }
        __syncthreads();
        #pragma unroll
        for (int mt=0; mt<2; mt++){
            int fA = mt*16 + q, fB = fA + 8;
            #pragma unroll
            for (int ng=0; ng<2; ng++){
                int l = 16*w + ng*8 + lc;
                float vals[4];
                vals[0] = geluf(acc1[mt][ng][0] + sb1[fA]);
                vals[1] = geluf(acc1[mt][ng][1] + sb1[fA]);
                vals[2] = geluf(acc1[mt][ng][2] + sb1[fB]);
                vals[3] = geluf(acc1[mt][ng][3] + sb1[fB]);
                #pragma unroll
                for (int j=0;j<4;j++){
                    int ff = (j<2) ? fA : fB;
                    int ll = l + (j&1);
                    __nv_bfloat16 hi = __float2bfloat16_rn(vals[j]);
                    __nv_bfloat16 lo = __float2bfloat16_rn(vals[j] - __bfloat162float(hi));
                    uint32_t off = (uint32_t)(ll*128 + (((ff>>3) ^ (ll&3))<<4) + ((ff&7)<<1));
                    *(unsigned short*)(sm + FO_H  + off) = __bfloat16_as_ushort(hi);
                    *(unsigned short*)(sm + FO_HL + off) = __bfloat16_as_ushort(lo);
                }
            }
        }
        __syncthreads();
        float acc2[2][8][4];
        #pragma unroll
        for (int mt=0;mt<2;mt++)
            #pragma unroll
            for (int nt=0;nt<8;nt++)
                #pragma unroll
                for (int r=0;r<4;r++) acc2[mt][nt][r] = 0.f;
        #pragma unroll
        for (int s=0; s<2; s++){
            int c = 2*s + chalf;
            uint32_t ah[2][4], al[2][4];
            #pragma unroll
            for (int mt=0; mt<2; mt++){
                int row = w*32 + mt*16 + (m&1)*8 + li;
                uint32_t adr = sbase + FO_W2 + (uint32_t)(row*128 + ((c ^ (row&3))<<4));
                LDM4(ah[mt][0],ah[mt][1],ah[mt][2],ah[mt][3], adr);
                LDM4(al[mt][0],al[mt][1],al[mt][2],al[mt][3], adr + (FO_W2L - FO_W2));
            }
            #pragma unroll
            for (int nb=0; nb<4; nb++){
                int brow = nb*16 + (m&1)*8 + li;
                uint32_t badr = sbase + FO_H + (uint32_t)(brow*128 + ((c ^ (brow&3))<<4));
                uint32_t bh[4], bl[4];
                LDM4(bh[0],bh[1],bh[2],bh[3], badr);
                LDM4(bl[0],bl[1],bl[2],bl[3], badr + (FO_HL - FO_H));
                #pragma unroll
                for (int mt=0; mt<2; mt++){
                    MMAB(acc2[mt][2*nb],   ah[mt], bh[0], bh[2]);
                    MMAB(acc2[mt][2*nb],   ah[mt], bl[0], bl[2]);
                    MMAB(acc2[mt][2*nb],   al[mt], bh[0], bh[2]);
                    MMAB(acc2[mt][2*nb+1], ah[mt], bh[1], bh[3]);
                    MMAB(acc2[mt][2*nb+1], ah[mt], bl[1], bl[3]);
                    MMAB(acc2[mt][2*nb+1], al[mt], bh[1], bh[3]);
                }
            }
        }
        #pragma unroll
        for (int mt=0; mt<2; mt++){
            int oA = w*32 + mt*16 + q, oB = oA + 8;
            float bvA = sb2[oA], bvB = sb2[oB];
            #pragma unroll
            for (int nt=0; nt<8; nt++){
                int l = nt*8 + lc;
                float pr[4];
                #pragma unroll
                for (int j=0;j<4;j++){
                    int o  = (j<2) ? oA : oB;
                    int ll = l + (j&1);
                    float y = geluf(acc2[mt][nt][j] + ((j<2)?bvA:bvB));
                    uint32_t off = (uint32_t)(ll*256 + (((o>>3) ^ (ll&7))<<4) + ((o&7)<<1));
                    float zh = __bfloat162float(__ushort_as_bfloat16(*(unsigned short*)(sm + FO_Z  + off)));
                    float zl = __bfloat162float(__ushort_as_bfloat16(*(unsigned short*)(sm + FO_ZL + off)));
                    float zin = zh + zl;
                    pr[j] = w0*y + w1*zin;
                    int sidx = mt*2 + (j>>1);
                    stS[sidx]  += pr[j];
                    stS2[sidx] += pr[j]*pr[j];
                }
                *(float2*)&pb0[(size_t)oA*LL + l0 + l] = make_float2(pr[0], pr[1]);
                *(float2*)&pb0[(size_t)oB*LL + l0 + l] = make_float2(pr[2], pr[3]);
            }
        }
    }
    #pragma unroll
    for (int j=0;j<4;j++){
        float s = stS[j], s2 = stS2[j];
        s  += __shfl_xor_sync(0xffffffffu, s, 1);
        s  += __shfl_xor_sync(0xffffffffu, s, 2);
        s2 += __shfl_xor_sync(0xffffffffu, s2, 1);
        s2 += __shfl_xor_sync(0xffffffffu, s2, 2);
        if ((lane & 3) == 0){
            int o = w*32 + (j>>1)*16 + q + (j&1)*8;
            atomicAdd(&g_stats[8*CC + o], (double)s);
            atomicAdd(&g_stats[9*CC + o], (double)s2);
        }
    }
}

// ------------------- final BN affine -> d_out -------------------
__global__ void K_final(float* __restrict__ out){
    size_t i = ((size_t)blockIdx.x*256 + threadIdx.x)*4;
    int c = (int)((i >> 14) & 127);
    float4 v = *(const float4*)&g_pre[i];
    float A = g_A2[c], Bc = g_B2[c];
    float4 r;
    r.x = A*v.x + Bc; r.y = A*v.y + Bc; r.z = A*v.z + Bc; r.w = A*v.w + Bc;
    *(float4*)&out[i] = r;
}

// ------------------- launch -------------------
extern "C" void kernel_launch(void* const* d_in, const int* in_sizes, int n_in,
                              void* d_out, int out_size){
    const float* x         = (const float*)d_in[0];
    const float* dw_w      = (const float*)d_in[1];
    const float* bn2_g     = (const float*)d_in[2];
    const float* bn2_b     = (const float*)d_in[3];
    const float* pw_w      = (const float*)d_in[4];
    const float* pw_b      = (const float*)d_in[5];
    const float* add_w     = (const float*)d_in[6];
    const float* bn1_g     = (const float*)d_in[7];
    const float* bn1_b     = (const float*)d_in[8];
    const float* W1        = (const float*)d_in[9];
    const float* b1        = (const float*)d_in[10];
    const float* W2        = (const float*)d_in[11];
    const float* b2        = (const float*)d_in[12];
    const float* ffn_add_w = (const float*)d_in[13];
    const float* ffn_bn_g  = (const float*)d_in[14];
    const float* ffn_bn_b  = (const float*)d_in[15];
    float* out = (float*)d_out;

    cudaFuncSetAttribute(K_pwkvT,  cudaFuncAttributeMaxDynamicSharedMemorySize, PWKV_SMEM);
    cudaFuncSetAttribute(K_pwattT, cudaFuncAttributeMaxDynamicSharedMemorySize, PWATT_SMEM);
    cudaFuncSetAttribute(K_ffnT,   cudaFuncAttributeMaxDynamicSharedMemorySize, FFN_SMEM);

    K_zero<<<128,256>>>();
    K_dw<<<dim3(2,CC,BB),256>>>(x, dw_w);
    K_prep<<<1,128>>>(bn2_g, bn2_b, pw_w, pw_b, W1, W2);
    K_pwkvT<<<dim3(LK/256,BB,2),256,PWKV_SMEM>>>();
    K_krow<<<BB*CC,256>>>();
    K_kv<<<dim3(BB*NH,4),256>>>();
    K_pwattT<<<dim3(LL/256,BB),256,PWATT_SMEM>>>(x, add_w);
    K_bnaff<<<1,128>>>(0, bn1_g, bn1_b);
    K_ffnT<<<dim3(LL/256,BB),128,FFN_SMEM>>>(b1, b2, ffn_add_w);
    K_bnaff<<<1,128>>>(1, ffn_bn_g, ffn_bn_b);
    K_final<<<(BB*CC*LL)/(256*4),256>>>(out);
}